// round 1
// baseline (speedup 1.0000x reference)
#include <cuda_runtime.h>
#include <math.h>

#define B_TOT 4096
#define B_HALF 2048

// ---------------- device scratch (no allocation allowed) ----------------
__device__ float g_zt[B_TOT * 64];     // relu(linear) features per row
__device__ float g_s[B_TOT];           // attention scores
__device__ float g_e[B_TOT];           // exp(s - m_g)
__device__ float g_S[2];               // per-group sum of exps
__device__ float g_P[128];             // per-group sum of e*zt  [2][64]
__device__ float g_pred[B_TOT * 128];  // pred rows
__device__ float g_pm[B_TOT * 4];      // per-row partial LSE max  (4 j-splits)
__device__ float g_pl[B_TOT * 4];      // per-row partial LSE sum
__device__ float g_diag[B_TOT];        // total[i][i]

// ---------------- Kernel A: zt = relu(zw@lw.T+lb); s = attn score ----------------
__global__ void __launch_bounds__(256) kA(const float* __restrict__ zw,
                                          const float* __restrict__ lw,
                                          const float* __restrict__ lb,
                                          const float* __restrict__ a1w,
                                          const float* __restrict__ a1b,
                                          const float* __restrict__ a2w,
                                          const float* __restrict__ a2b,
                                          int base) {
    __shared__ float s_zw[16][128];
    __shared__ float s_zt[16][64];
    __shared__ float s_h[16][32];
    int r0 = blockIdx.x * 16;
    int tid = threadIdx.x;
    for (int idx = tid; idx < 16 * 128; idx += 256)
        s_zw[idx >> 7][idx & 127] = zw[r0 * 128 + idx];
    __syncthreads();
    for (int idx = tid; idx < 16 * 64; idx += 256) {
        int r = idx >> 6, k = idx & 63;
        const float* w = lw + k * 128;
        float acc = lb[k];
#pragma unroll 16
        for (int kk = 0; kk < 128; ++kk) acc = fmaf(w[kk], s_zw[r][kk], acc);
        acc = fmaxf(acc, 0.f);
        s_zt[r][k] = acc;
        g_zt[(base + r0 + r) * 64 + k] = acc;
    }
    __syncthreads();
    for (int idx = tid; idx < 16 * 32; idx += 256) {
        int r = idx >> 5, u = idx & 31;
        const float* w = a1w + u * 64;
        float acc = a1b[u];
#pragma unroll 16
        for (int kk = 0; kk < 64; ++kk) acc = fmaf(w[kk], s_zt[r][kk], acc);
        s_h[r][u] = tanhf(acc);
    }
    __syncthreads();
    if (tid < 16) {
        float acc = a2b[0];
#pragma unroll
        for (int u = 0; u < 32; ++u) acc = fmaf(a2w[u], s_h[tid][u], acc);
        g_s[base + r0 + tid] = acc;
    }
}

// ---------------- Kernel B: per-group m, e, S, P ----------------
__global__ void __launch_bounds__(256) kB() {
    int g = blockIdx.x;
    int tid = threadIdx.x;
    const float* s = g_s + g * B_HALF;
    __shared__ float red[256];
    float m = -1e30f;
    for (int j = tid; j < B_HALF; j += 256) m = fmaxf(m, s[j]);
    red[tid] = m;
    __syncthreads();
    for (int w = 128; w > 0; w >>= 1) {
        if (tid < w) red[tid] = fmaxf(red[tid], red[tid + w]);
        __syncthreads();
    }
    m = red[0];
    __syncthreads();
    float lsum = 0.f;
    for (int j = tid; j < B_HALF; j += 256) {
        float e = __expf(s[j] - m);
        g_e[g * B_HALF + j] = e;
        lsum += e;
    }
    red[tid] = lsum;
    __syncthreads();
    for (int w = 128; w > 0; w >>= 1) {
        if (tid < w) red[tid] += red[tid + w];
        __syncthreads();
    }
    if (tid == 0) g_S[g] = red[0];
    __syncthreads();
    if (tid < 64) {
        const float* zt = g_zt + g * B_HALF * 64;
        const float* e = g_e + g * B_HALF;
        float p = 0.f;
        for (int j = 0; j < B_HALF; ++j) p = fmaf(e[j], zt[j * 64 + tid], p);
        g_P[g * 64 + tid] = p;
    }
}

// ---------------- Kernel C: pooled (LOO) -> pred = Ww@pooled + b + c@Wk.T + bk ----------------
__global__ void __launch_bounds__(128) kC(const float* __restrict__ c,
                                          const float* __restrict__ Wk_w,
                                          const float* __restrict__ Wk_b,
                                          const float* __restrict__ Ww0_w,
                                          const float* __restrict__ Ww0_b,
                                          const float* __restrict__ Ww1_w,
                                          const float* __restrict__ Ww1_b) {
    int i0 = blockIdx.x * 8;
    int g = (i0 >= B_HALF) ? 1 : 0;
    const float* Ww = g ? Ww1_w : Ww0_w;
    const float* Wb = g ? Ww1_b : Ww0_b;
    __shared__ float sp[8][64];
    __shared__ float sc[8][64];
    int tid = threadIdx.x;
    float S = g_S[g];
    const float* P = g_P + g * 64;
    for (int idx = tid; idx < 512; idx += 128) {
        int r = idx >> 6, k = idx & 63;
        int i = i0 + r;
        float e = g_e[i];
        sp[r][k] = (P[k] - e * g_zt[i * 64 + k]) / (S - e);
        sc[r][k] = c[i * 64 + k];
    }
    __syncthreads();
    int o = tid;
    const float* ww = Ww + o * 64;
    const float* wk = Wk_w + o * 64;
    float wb = Wb[o] + Wk_b[o];
    for (int r = 0; r < 8; ++r) {
        float acc = wb;
#pragma unroll 16
        for (int k = 0; k < 64; ++k)
            acc = fmaf(ww[k], sp[r][k], fmaf(wk[k], sc[r][k], acc));
        g_pred[(i0 + r) * 128 + o] = acc;
    }
}

// ---------------- Kernel D: fused zw@pred.T + online row-LSE + diag capture ----------------
// grid (64 i-blocks, 4 j-splits), 256 threads. Tile 64i x 32j, k=128.
__global__ void __launch_bounds__(256) kD(const float* __restrict__ zw0,
                                          const float* __restrict__ zw1) {
    __shared__ float sA[128 * 64];  // [k][i]  32KB
    __shared__ float sB[128 * 32];  // [k][j]  16KB
    int i0 = blockIdx.x * 64;
    const float* zw = (i0 < B_HALF) ? (zw0 + i0 * 128) : (zw1 + (i0 - B_HALF) * 128);
    int tid = threadIdx.x;
    for (int idx = tid; idx < 64 * 128; idx += 256) {
        int i = idx & 63, k = idx >> 6;
        sA[k * 64 + i] = zw[i * 128 + k];
    }
    int tx = tid & 7;    // 8 groups x 4 j  = 32
    int ty = tid >> 3;   // 32 groups x 2 i = 64
    float rm[2] = {-1e30f, -1e30f};
    float rl[2] = {0.f, 0.f};
    int jsplit0 = blockIdx.y * 1024;
    for (int jt = 0; jt < 32; ++jt) {
        int jbase = jsplit0 + jt * 32;
        __syncthreads();
        for (int idx = tid; idx < 32 * 128; idx += 256) {
            int j = idx & 31, k = idx >> 5;
            sB[k * 32 + j] = g_pred[(jbase + j) * 128 + k];
        }
        __syncthreads();
        float acc[2][4];
#pragma unroll
        for (int a = 0; a < 2; ++a)
#pragma unroll
            for (int b = 0; b < 4; ++b) acc[a][b] = 0.f;
#pragma unroll 4
        for (int k = 0; k < 128; ++k) {
            float2 av = *(const float2*)&sA[k * 64 + ty * 2];
            float4 bv = *(const float4*)&sB[k * 32 + tx * 4];
            acc[0][0] = fmaf(av.x, bv.x, acc[0][0]);
            acc[0][1] = fmaf(av.x, bv.y, acc[0][1]);
            acc[0][2] = fmaf(av.x, bv.z, acc[0][2]);
            acc[0][3] = fmaf(av.x, bv.w, acc[0][3]);
            acc[1][0] = fmaf(av.y, bv.x, acc[1][0]);
            acc[1][1] = fmaf(av.y, bv.y, acc[1][1]);
            acc[1][2] = fmaf(av.y, bv.z, acc[1][2]);
            acc[1][3] = fmaf(av.y, bv.w, acc[1][3]);
        }
#pragma unroll
        for (int ii = 0; ii < 2; ++ii) {
            int irow = i0 + ty * 2 + ii;
            float tmax = fmaxf(fmaxf(acc[ii][0], acc[ii][1]),
                               fmaxf(acc[ii][2], acc[ii][3]));
            if (tmax > rm[ii]) {
                rl[ii] *= __expf(rm[ii] - tmax);
                rm[ii] = tmax;
            }
#pragma unroll
            for (int jj = 0; jj < 4; ++jj)
                rl[ii] += __expf(acc[ii][jj] - rm[ii]);
            int dj = irow - jbase - tx * 4;
            if (dj >= 0 && dj < 4) {
                float dv = (dj == 0) ? acc[ii][0]
                         : (dj == 1) ? acc[ii][1]
                         : (dj == 2) ? acc[ii][2]
                                     : acc[ii][3];
                g_diag[irow] = dv;
            }
        }
    }
    __syncthreads();
    // combine the 8 tx-partials per row (reuse sB)
    float* pm = sB;             // [64][8]
    float* pl = sB + 64 * 8;    // [64][8]
#pragma unroll
    for (int ii = 0; ii < 2; ++ii) {
        int r = ty * 2 + ii;
        pm[r * 8 + tx] = rm[ii];
        pl[r * 8 + tx] = rl[ii];
    }
    __syncthreads();
    if (tid < 64) {
        float m = -1e30f;
#pragma unroll
        for (int t = 0; t < 8; ++t) m = fmaxf(m, pm[tid * 8 + t]);
        float l = 0.f;
#pragma unroll
        for (int t = 0; t < 8; ++t) l += pl[tid * 8 + t] * __expf(pm[tid * 8 + t] - m);
        int irow = i0 + tid;
        g_pm[irow * 4 + blockIdx.y] = m;
        g_pl[irow * 4 + blockIdx.y] = l;
    }
}

// ---------------- Kernel E: combine splits, final scalar (deterministic) ----------------
__global__ void __launch_bounds__(1024) kE(float* out) {
    __shared__ float red[1024];
    int tid = threadIdx.x;
    float local = 0.f;
    for (int i = tid; i < B_TOT; i += 1024) {
        float m = -1e30f;
#pragma unroll
        for (int s = 0; s < 4; ++s) m = fmaxf(m, g_pm[i * 4 + s]);
        float l = 0.f;
#pragma unroll
        for (int s = 0; s < 4; ++s) l += g_pl[i * 4 + s] * __expf(g_pm[i * 4 + s] - m);
        local += (m + logf(l)) - g_diag[i];
    }
    red[tid] = local;
    __syncthreads();
    for (int w = 512; w > 0; w >>= 1) {
        if (tid < w) red[tid] += red[tid + w];
        __syncthreads();
    }
    if (tid == 0) out[0] = red[0] / (float)B_TOT;
}

extern "C" void kernel_launch(void* const* d_in, const int* in_sizes, int n_in,
                              void* d_out, int out_size) {
    const float* zw0   = (const float*)d_in[0];
    const float* zw1   = (const float*)d_in[1];
    const float* c     = (const float*)d_in[2];
    const float* Wk_w  = (const float*)d_in[3];
    const float* Wk_b  = (const float*)d_in[4];
    const float* Ww0_w = (const float*)d_in[5];
    const float* Ww0_b = (const float*)d_in[6];
    const float* Ww1_w = (const float*)d_in[7];
    const float* Ww1_b = (const float*)d_in[8];
    const float* lin0_w = (const float*)d_in[9];
    const float* lin0_b = (const float*)d_in[10];
    const float* lin1_w = (const float*)d_in[11];
    const float* lin1_b = (const float*)d_in[12];
    const float* a01w = (const float*)d_in[13];
    const float* a01b = (const float*)d_in[14];
    const float* a02w = (const float*)d_in[15];
    const float* a02b = (const float*)d_in[16];
    const float* a11w = (const float*)d_in[17];
    const float* a11b = (const float*)d_in[18];
    const float* a12w = (const float*)d_in[19];
    const float* a12b = (const float*)d_in[20];

    kA<<<128, 256>>>(zw0, lin0_w, lin0_b, a01w, a01b, a02w, a02b, 0);
    kA<<<128, 256>>>(zw1, lin1_w, lin1_b, a11w, a11b, a12w, a12b, B_HALF);
    kB<<<2, 256>>>();
    kC<<<512, 128>>>(c, Wk_w, Wk_b, Ww0_w, Ww0_b, Ww1_w, Ww1_b);
    kD<<<dim3(64, 4), 256>>>(zw0, zw1);
    kE<<<1, 1024>>>((float*)d_out);
}

// round 4
// speedup vs baseline: 1.8601x; 1.8601x over previous
#include <cuda_runtime.h>
#include <math.h>

#define B_TOT 4096
#define B_HALF 2048
#define NS 8            // j-splits in kD
#define KC 32           // k-chunk in kD
#define TI 128          // i-tile per block in kD
#define TJ 64           // j-tile in kD
#define SAS 132         // padded row stride (floats): 528B, 16B-aligned

// ---------------- device scratch ----------------
__device__ float g_zt[B_TOT * 64];
__device__ float g_s[B_TOT];
__device__ float g_e[B_TOT];
__device__ float g_S[2];
__device__ float g_P[128];
__device__ float g_pred[B_TOT * 128];
__device__ float g_pm[B_TOT * NS];
__device__ float g_pl[B_TOT * NS];
__device__ float g_diag[B_TOT];

// packed f32x2 FMA (sm_100+): d = a*b + d elementwise on two packed floats
__device__ __forceinline__ void ffma2(unsigned long long& d, unsigned long long a,
                                      unsigned long long b) {
    asm("fma.rn.f32x2 %0, %1, %2, %0;" : "+l"(d) : "l"(a), "l"(b));
}
__device__ __forceinline__ float2 up2(unsigned long long v) {
    float2 r;
    asm("mov.b64 {%0, %1}, %2;" : "=f"(r.x), "=f"(r.y) : "l"(v));
    return r;
}

// ---------------- Kernel A: zt = relu(zw@lw.T+lb); s = attn score ----------------
__global__ void __launch_bounds__(256) kA(const float* __restrict__ zw,
                                          const float* __restrict__ lw,
                                          const float* __restrict__ lb,
                                          const float* __restrict__ a1w,
                                          const float* __restrict__ a1b,
                                          const float* __restrict__ a2w,
                                          const float* __restrict__ a2b,
                                          int base) {
    __shared__ float s_zw[16][128];
    __shared__ float s_zt[16][64];
    __shared__ float s_h[16][32];
    int r0 = blockIdx.x * 16;
    int tid = threadIdx.x;
    for (int idx = tid; idx < 16 * 128; idx += 256)
        s_zw[idx >> 7][idx & 127] = zw[r0 * 128 + idx];
    __syncthreads();
    for (int idx = tid; idx < 16 * 64; idx += 256) {
        int r = idx >> 6, k = idx & 63;
        const float* w = lw + k * 128;
        float acc = lb[k];
#pragma unroll 16
        for (int kk = 0; kk < 128; ++kk) acc = fmaf(w[kk], s_zw[r][kk], acc);
        acc = fmaxf(acc, 0.f);
        s_zt[r][k] = acc;
        g_zt[(base + r0 + r) * 64 + k] = acc;
    }
    __syncthreads();
    for (int idx = tid; idx < 16 * 32; idx += 256) {
        int r = idx >> 5, u = idx & 31;
        const float* w = a1w + u * 64;
        float acc = a1b[u];
#pragma unroll 16
        for (int kk = 0; kk < 64; ++kk) acc = fmaf(w[kk], s_zt[r][kk], acc);
        s_h[r][u] = tanhf(acc);
    }
    __syncthreads();
    if (tid < 16) {
        float acc = a2b[0];
#pragma unroll
        for (int u = 0; u < 32; ++u) acc = fmaf(a2w[u], s_h[tid][u], acc);
        g_s[base + r0 + tid] = acc;
    }
}

// ---------------- Kernel B: per-group m, e, S, P (parallel P) ----------------
__global__ void __launch_bounds__(256) kB() {
    int g = blockIdx.x;
    int tid = threadIdx.x;
    const float* s = g_s + g * B_HALF;
    __shared__ float red[256];
    __shared__ float red2[4][64];
    float m = -1e30f;
    for (int j = tid; j < B_HALF; j += 256) m = fmaxf(m, s[j]);
    red[tid] = m;
    __syncthreads();
    for (int w = 128; w > 0; w >>= 1) {
        if (tid < w) red[tid] = fmaxf(red[tid], red[tid + w]);
        __syncthreads();
    }
    m = red[0];
    __syncthreads();
    float lsum = 0.f;
    for (int j = tid; j < B_HALF; j += 256) {
        float e = __expf(s[j] - m);
        g_e[g * B_HALF + j] = e;
        lsum += e;
    }
    red[tid] = lsum;
    __syncthreads();
    for (int w = 128; w > 0; w >>= 1) {
        if (tid < w) red[tid] += red[tid + w];
        __syncthreads();
    }
    if (tid == 0) g_S[g] = red[0];
    __syncthreads();
    // P[k] = sum_j e[j] * zt[j][k]  — 64 k-cols x 4 j-slices
    int k = tid & 63, sl = tid >> 6;
    const float* zt = g_zt + g * B_HALF * 64;
    const float* e = g_e + g * B_HALF;
    float p0 = 0.f, p1 = 0.f;
    int j0 = sl * 512;
#pragma unroll 4
    for (int j = j0; j < j0 + 512; j += 2) {
        p0 = fmaf(e[j], zt[j * 64 + k], p0);
        p1 = fmaf(e[j + 1], zt[(j + 1) * 64 + k], p1);
    }
    red2[sl][k] = p0 + p1;
    __syncthreads();
    if (tid < 64)
        g_P[g * 64 + tid] =
            red2[0][tid] + red2[1][tid] + red2[2][tid] + red2[3][tid];
}

// ---------------- Kernel C: pred = [pooled|c] @ [Ww|Wk]^T + biases (tiled GEMM) ----------------
// grid (128 rowblocks of 32, 2 colblocks of 64), 256 threads
__global__ void __launch_bounds__(256) kC(const float* __restrict__ c,
                                          const float* __restrict__ Wk_w,
                                          const float* __restrict__ Wk_b,
                                          const float* __restrict__ Ww0_w,
                                          const float* __restrict__ Ww0_b,
                                          const float* __restrict__ Ww1_w,
                                          const float* __restrict__ Ww1_b) {
    __shared__ __align__(16) float feat[32][SAS];  // 32 rows x 128 features
    __shared__ __align__(16) float W[64][SAS];     // 64 out cols x 128
    int r0 = blockIdx.x * 32;
    int c0 = blockIdx.y * 64;
    int g = (r0 >= B_HALF) ? 1 : 0;
    const float* Ww = g ? Ww1_w : Ww0_w;
    const float* Wb = g ? Ww1_b : Ww0_b;
    int tid = threadIdx.x;
    float S = g_S[g];
    const float* P = g_P + g * 64;
    for (int idx = tid; idx < 32 * 128; idx += 256) {
        int r = idx >> 7, k = idx & 127;
        int i = r0 + r;
        float v;
        if (k < 64) {
            float e = g_e[i];
            v = (P[k] - e * g_zt[i * 64 + k]) / (S - e);
        } else {
            v = c[i * 64 + (k - 64)];
        }
        feat[r][k] = v;
    }
    for (int idx = tid; idx < 64 * 128; idx += 256) {
        int o = idx >> 7, k = idx & 127;
        W[o][k] = (k < 64) ? Ww[(c0 + o) * 64 + k] : Wk_w[(c0 + o) * 64 + (k - 64)];
    }
    __syncthreads();
    int tx = tid & 63, ty = tid >> 6;  // ty: 4 groups of 8 rows
    float acc[8];
    float b = Wb[c0 + tx] + Wk_b[c0 + tx];
#pragma unroll
    for (int r = 0; r < 8; ++r) acc[r] = b;
#pragma unroll 8
    for (int k4 = 0; k4 < 32; ++k4) {
        float4 w = *(const float4*)&W[tx][k4 * 4];
#pragma unroll
        for (int r = 0; r < 8; ++r) {
            float4 f = *(const float4*)&feat[ty * 8 + r][k4 * 4];
            acc[r] = fmaf(w.x, f.x, acc[r]);
            acc[r] = fmaf(w.y, f.y, acc[r]);
            acc[r] = fmaf(w.z, f.z, acc[r]);
            acc[r] = fmaf(w.w, f.w, acc[r]);
        }
    }
#pragma unroll
    for (int r = 0; r < 8; ++r)
        g_pred[(r0 + ty * 8 + r) * 128 + c0 + tx] = acc[r];
}

// ---------------- Kernel D: fused zw@pred.T + online row-LSE (packed f32x2 FMA) ----------------
// grid (32 i-blocks of 128, NS j-splits of 512), 256 threads.
// Per thread: 8 i (4 packed pairs) x 4 j.  B tile stored duplicated so j-broadcast
// pairs load pre-packed via LDS.128.  Global->smem staging is software-pipelined:
// the next chunk's LDGs issue before the current chunk's compute.
__global__ void __launch_bounds__(256) kD(const float* __restrict__ zw0,
                                          const float* __restrict__ zw1) {
    __shared__ __align__(16) float sA[KC][SAS];        // [k][i]  chunk
    __shared__ __align__(16) float sBd[KC][SAS];       // [k][2j] duplicated chunk
    int i0 = blockIdx.x * TI;
    int tid = threadIdx.x;
    int jg = tid & 15;   // 16 j-groups x 4 j
    int ig = tid >> 4;   // 16 i-groups x 8 i
    const float* zw = (i0 < B_HALF) ? (zw0 + i0 * 128) : (zw1 + (i0 - B_HALF) * 128);
    float rm[8], rl[8];
#pragma unroll
    for (int r = 0; r < 8; ++r) { rm[r] = -1e30f; rl[r] = 0.f; }
    int js0 = blockIdx.y * (B_TOT / NS);

    // per-thread staging indices (fixed across chunks)
    int ai[16], ak[16];
#pragma unroll
    for (int u = 0; u < 16; ++u) {
        int idx = tid + u * 256;
        ai[u] = idx >> 5;
        ak[u] = idx & 31;
    }
    int bj[8], bk[8];
#pragma unroll
    for (int u = 0; u < 8; ++u) {
        int idx = tid + u * 256;
        bj[u] = idx >> 5;
        bk[u] = idx & 31;
    }

    float a_reg[16], b_reg[8];

    for (int jt = 0; jt < (B_TOT / NS) / TJ; ++jt) {
        int jbase = js0 + jt * TJ;
        unsigned long long acc[4][4];
#pragma unroll
        for (int p = 0; p < 4; ++p)
#pragma unroll
            for (int j = 0; j < 4; ++j) acc[p][j] = 0ull;

        // prefetch chunk kc=0
#pragma unroll
        for (int u = 0; u < 16; ++u) a_reg[u] = zw[ai[u] * 128 + ak[u]];
#pragma unroll
        for (int u = 0; u < 8; ++u) b_reg[u] = g_pred[(jbase + bj[u]) * 128 + bk[u]];

        for (int kc = 0; kc < 128; kc += KC) {
            __syncthreads();  // previous compute done reading smem
#pragma unroll
            for (int u = 0; u < 16; ++u) sA[ak[u]][ai[u]] = a_reg[u];
#pragma unroll
            for (int u = 0; u < 8; ++u)
                *(float2*)&sBd[bk[u]][2 * bj[u]] = make_float2(b_reg[u], b_reg[u]);
            __syncthreads();
            // issue next chunk's LDGs before compute (overlap latency)
            if (kc + KC < 128) {
                int kn = kc + KC;
#pragma unroll
                for (int u = 0; u < 16; ++u) a_reg[u] = zw[ai[u] * 128 + kn + ak[u]];
#pragma unroll
                for (int u = 0; u < 8; ++u)
                    b_reg[u] = g_pred[(jbase + bj[u]) * 128 + kn + bk[u]];
            }
#pragma unroll 8
            for (int k = 0; k < KC; ++k) {
                ulonglong2 A0 = *(const ulonglong2*)&sA[k][ig * 8];
                ulonglong2 A1 = *(const ulonglong2*)&sA[k][ig * 8 + 4];
                ulonglong2 B0 = *(const ulonglong2*)&sBd[k][jg * 8];
                ulonglong2 B1 = *(const ulonglong2*)&sBd[k][jg * 8 + 4];
                ffma2(acc[0][0], A0.x, B0.x);
                ffma2(acc[0][1], A0.x, B0.y);
                ffma2(acc[0][2], A0.x, B1.x);
                ffma2(acc[0][3], A0.x, B1.y);
                ffma2(acc[1][0], A0.y, B0.x);
                ffma2(acc[1][1], A0.y, B0.y);
                ffma2(acc[1][2], A0.y, B1.x);
                ffma2(acc[1][3], A0.y, B1.y);
                ffma2(acc[2][0], A1.x, B0.x);
                ffma2(acc[2][1], A1.x, B0.y);
                ffma2(acc[2][2], A1.x, B1.x);
                ffma2(acc[2][3], A1.x, B1.y);
                ffma2(acc[3][0], A1.y, B0.x);
                ffma2(acc[3][1], A1.y, B0.y);
                ffma2(acc[3][2], A1.y, B1.x);
                ffma2(acc[3][3], A1.y, B1.y);
            }
        }
        // epilogue: unpack, online LSE, diag capture
#pragma unroll
        for (int p = 0; p < 4; ++p) {
            float2 v0 = up2(acc[p][0]);
            float2 v1 = up2(acc[p][1]);
            float2 v2 = up2(acc[p][2]);
            float2 v3 = up2(acc[p][3]);
#pragma unroll
            for (int h = 0; h < 2; ++h) {
                int r = p * 2 + h;
                float a0 = h ? v0.y : v0.x;
                float a1 = h ? v1.y : v1.x;
                float a2 = h ? v2.y : v2.x;
                float a3 = h ? v3.y : v3.x;
                float tmax = fmaxf(fmaxf(a0, a1), fmaxf(a2, a3));
                if (tmax > rm[r]) {
                    rl[r] *= __expf(rm[r] - tmax);
                    rm[r] = tmax;
                }
                rl[r] += __expf(a0 - rm[r]) + __expf(a1 - rm[r]) +
                         __expf(a2 - rm[r]) + __expf(a3 - rm[r]);
                int irow = i0 + ig * 8 + r;
                int dj = irow - (jbase + jg * 4);
                if (dj >= 0 && dj < 4) {
                    float dv = (dj == 0) ? a0 : (dj == 1) ? a1 : (dj == 2) ? a2 : a3;
                    g_diag[irow] = dv;
                }
            }
        }
    }
    __syncthreads();
    // combine 16 jg-partials per row (reuse smem)
    float* pm = &sA[0][0];   // [128][16]
    float* pl = &sBd[0][0];  // [128][16]
#pragma unroll
    for (int r = 0; r < 8; ++r) {
        int row = ig * 8 + r;
        pm[row * 16 + jg] = rm[r];
        pl[row * 16 + jg] = rl[r];
    }
    __syncthreads();
    if (tid < 128) {
        float m = -1e30f;
#pragma unroll
        for (int t = 0; t < 16; ++t) m = fmaxf(m, pm[tid * 16 + t]);
        float l = 0.f;
#pragma unroll
        for (int t = 0; t < 16; ++t) l += pl[tid * 16 + t] * __expf(pm[tid * 16 + t] - m);
        int irow = i0 + tid;
        g_pm[irow * NS + blockIdx.y] = m;
        g_pl[irow * NS + blockIdx.y] = l;
    }
}

// ---------------- Kernel E: combine splits, final scalar ----------------
__global__ void __launch_bounds__(1024) kE(float* out) {
    __shared__ float red[1024];
    int tid = threadIdx.x;
    float local = 0.f;
    for (int i = tid; i < B_TOT; i += 1024) {
        float m = -1e30f;
#pragma unroll
        for (int s = 0; s < NS; ++s) m = fmaxf(m, g_pm[i * NS + s]);
        float l = 0.f;
#pragma unroll
        for (int s = 0; s < NS; ++s) l += g_pl[i * NS + s] * __expf(g_pm[i * NS + s] - m);
        local += (m + logf(l)) - g_diag[i];
    }
    red[tid] = local;
    __syncthreads();
    for (int w = 512; w > 0; w >>= 1) {
        if (tid < w) red[tid] += red[tid + w];
        __syncthreads();
    }
    if (tid == 0) out[0] = red[0] / (float)B_TOT;
}

extern "C" void kernel_launch(void* const* d_in, const int* in_sizes, int n_in,
                              void* d_out, int out_size) {
    const float* zw0   = (const float*)d_in[0];
    const float* zw1   = (const float*)d_in[1];
    const float* c     = (const float*)d_in[2];
    const float* Wk_w  = (const float*)d_in[3];
    const float* Wk_b  = (const float*)d_in[4];
    const float* Ww0_w = (const float*)d_in[5];
    const float* Ww0_b = (const float*)d_in[6];
    const float* Ww1_w = (const float*)d_in[7];
    const float* Ww1_b = (const float*)d_in[8];
    const float* lin0_w = (const float*)d_in[9];
    const float* lin0_b = (const float*)d_in[10];
    const float* lin1_w = (const float*)d_in[11];
    const float* lin1_b = (const float*)d_in[12];
    const float* a01w = (const float*)d_in[13];
    const float* a01b = (const float*)d_in[14];
    const float* a02w = (const float*)d_in[15];
    const float* a02b = (const float*)d_in[16];
    const float* a11w = (const float*)d_in[17];
    const float* a11b = (const float*)d_in[18];
    const float* a12w = (const float*)d_in[19];
    const float* a12b = (const float*)d_in[20];

    kA<<<128, 256>>>(zw0, lin0_w, lin0_b, a01w, a01b, a02w, a02b, 0);
    kA<<<128, 256>>>(zw1, lin1_w, lin1_b, a11w, a11b, a12w, a12b, B_HALF);
    kB<<<2, 256>>>();
    kC<<<dim3(128, 2), 256>>>(c, Wk_w, Wk_b, Ww0_w, Ww0_b, Ww1_w, Ww1_b);
    kD<<<dim3(32, NS), 256>>>(zw0, zw1);
    kE<<<1, 1024>>>((float*)d_out);
}

// round 6
// speedup vs baseline: 2.2038x; 1.1848x over previous
#include <cuda_runtime.h>
#include <math.h>

#define B_TOT 4096
#define B_HALF 2048
#define NS 8            // j-splits in kD
#define KC 16           // k-chunk in kD
#define SAS 132         // kC pad

// ---------------- device scratch ----------------
__device__ float g_zt[B_TOT * 64];
__device__ float g_s[B_TOT];
__device__ float g_e[B_TOT];
__device__ float g_S[2];
__device__ float g_P[128];
__device__ float g_pred[B_TOT * 128];
__device__ float g_pm[B_TOT * NS];
__device__ float g_pl[B_TOT * NS];
__device__ float g_diag[B_TOT];

// packed f32x2 FMA (sm_100+): d = a*b + d elementwise on two packed floats
__device__ __forceinline__ void ffma2(unsigned long long& d, unsigned long long a,
                                      unsigned long long b) {
    asm("fma.rn.f32x2 %0, %1, %2, %0;" : "+l"(d) : "l"(a), "l"(b));
}
__device__ __forceinline__ float2 up2(unsigned long long v) {
    float2 r;
    asm("mov.b64 {%0, %1}, %2;" : "=f"(r.x), "=f"(r.y) : "l"(v));
    return r;
}

// ---------------- Kernel A ----------------
__global__ void __launch_bounds__(256) kA(const float* __restrict__ zw,
                                          const float* __restrict__ lw,
                                          const float* __restrict__ lb,
                                          const float* __restrict__ a1w,
                                          const float* __restrict__ a1b,
                                          const float* __restrict__ a2w,
                                          const float* __restrict__ a2b,
                                          int base) {
    __shared__ float s_zw[16][128];
    __shared__ float s_zt[16][64];
    __shared__ float s_h[16][32];
    int r0 = blockIdx.x * 16;
    int tid = threadIdx.x;
    for (int idx = tid; idx < 16 * 128; idx += 256)
        s_zw[idx >> 7][idx & 127] = zw[r0 * 128 + idx];
    __syncthreads();
    for (int idx = tid; idx < 16 * 64; idx += 256) {
        int r = idx >> 6, k = idx & 63;
        const float* w = lw + k * 128;
        float acc = lb[k];
#pragma unroll 16
        for (int kk = 0; kk < 128; ++kk) acc = fmaf(w[kk], s_zw[r][kk], acc);
        acc = fmaxf(acc, 0.f);
        s_zt[r][k] = acc;
        g_zt[(base + r0 + r) * 64 + k] = acc;
    }
    __syncthreads();
    for (int idx = tid; idx < 16 * 32; idx += 256) {
        int r = idx >> 5, u = idx & 31;
        const float* w = a1w + u * 64;
        float acc = a1b[u];
#pragma unroll 16
        for (int kk = 0; kk < 64; ++kk) acc = fmaf(w[kk], s_zt[r][kk], acc);
        s_h[r][u] = tanhf(acc);
    }
    __syncthreads();
    if (tid < 16) {
        float acc = a2b[0];
#pragma unroll
        for (int u = 0; u < 32; ++u) acc = fmaf(a2w[u], s_h[tid][u], acc);
        g_s[base + r0 + tid] = acc;
    }
}

// ---------------- Kernel B ----------------
__global__ void __launch_bounds__(256) kB() {
    int g = blockIdx.x;
    int tid = threadIdx.x;
    const float* s = g_s + g * B_HALF;
    __shared__ float red[256];
    __shared__ float red2[4][64];
    float m = -1e30f;
    for (int j = tid; j < B_HALF; j += 256) m = fmaxf(m, s[j]);
    red[tid] = m;
    __syncthreads();
    for (int w = 128; w > 0; w >>= 1) {
        if (tid < w) red[tid] = fmaxf(red[tid], red[tid + w]);
        __syncthreads();
    }
    m = red[0];
    __syncthreads();
    float lsum = 0.f;
    for (int j = tid; j < B_HALF; j += 256) {
        float e = __expf(s[j] - m);
        g_e[g * B_HALF + j] = e;
        lsum += e;
    }
    red[tid] = lsum;
    __syncthreads();
    for (int w = 128; w > 0; w >>= 1) {
        if (tid < w) red[tid] += red[tid + w];
        __syncthreads();
    }
    if (tid == 0) g_S[g] = red[0];
    __syncthreads();
    int k = tid & 63, sl = tid >> 6;
    const float* zt = g_zt + g * B_HALF * 64;
    const float* e = g_e + g * B_HALF;
    float p0 = 0.f, p1 = 0.f;
    int j0 = sl * 512;
#pragma unroll 4
    for (int j = j0; j < j0 + 512; j += 2) {
        p0 = fmaf(e[j], zt[j * 64 + k], p0);
        p1 = fmaf(e[j + 1], zt[(j + 1) * 64 + k], p1);
    }
    red2[sl][k] = p0 + p1;
    __syncthreads();
    if (tid < 64)
        g_P[g * 64 + tid] =
            red2[0][tid] + red2[1][tid] + red2[2][tid] + red2[3][tid];
}

// ---------------- Kernel C: tiled GEMM ----------------
__global__ void __launch_bounds__(256) kC(const float* __restrict__ c,
                                          const float* __restrict__ Wk_w,
                                          const float* __restrict__ Wk_b,
                                          const float* __restrict__ Ww0_w,
                                          const float* __restrict__ Ww0_b,
                                          const float* __restrict__ Ww1_w,
                                          const float* __restrict__ Ww1_b) {
    __shared__ __align__(16) float feat[32][SAS];
    __shared__ __align__(16) float W[64][SAS];
    int r0 = blockIdx.x * 32;
    int c0 = blockIdx.y * 64;
    int g = (r0 >= B_HALF) ? 1 : 0;
    const float* Ww = g ? Ww1_w : Ww0_w;
    const float* Wb = g ? Ww1_b : Ww0_b;
    int tid = threadIdx.x;
    float S = g_S[g];
    const float* P = g_P + g * 64;
    for (int idx = tid; idx < 32 * 128; idx += 256) {
        int r = idx >> 7, k = idx & 127;
        int i = r0 + r;
        float v;
        if (k < 64) {
            float e = g_e[i];
            v = (P[k] - e * g_zt[i * 64 + k]) / (S - e);
        } else {
            v = c[i * 64 + (k - 64)];
        }
        feat[r][k] = v;
    }
    for (int idx = tid; idx < 64 * 128; idx += 256) {
        int o = idx >> 7, k = idx & 127;
        W[o][k] = (k < 64) ? Ww[(c0 + o) * 64 + k] : Wk_w[(c0 + o) * 64 + (k - 64)];
    }
    __syncthreads();
    int tx = tid & 63, ty = tid >> 6;
    float acc[8];
    float b = Wb[c0 + tx] + Wk_b[c0 + tx];
#pragma unroll
    for (int r = 0; r < 8; ++r) acc[r] = b;
#pragma unroll 8
    for (int k4 = 0; k4 < 32; ++k4) {
        float4 w = *(const float4*)&W[tx][k4 * 4];
#pragma unroll
        for (int r = 0; r < 8; ++r) {
            float4 f = *(const float4*)&feat[ty * 8 + r][k4 * 4];
            acc[r] = fmaf(w.x, f.x, acc[r]);
            acc[r] = fmaf(w.y, f.y, acc[r]);
            acc[r] = fmaf(w.z, f.z, acc[r]);
            acc[r] = fmaf(w.w, f.w, acc[r]);
        }
    }
#pragma unroll
    for (int r = 0; r < 8; ++r)
        g_pred[(r0 + ty * 8 + r) * 128 + c0 + tx] = acc[r];
}

// ---------------- Kernel D: fused zw@pred.T + online row-LSE ----------------
// grid (32 i-blocks of 128, NS j-splits of 512), 256 threads.
// Thread tile 8i x 8j via FFMA2 (acc[4 i-pairs][8 j]).  B stored duplicated in
// 4 quarter-rows of 64 floats so each 8-lane LDS.128 phase reads a contiguous
// 128B window (conflict-free).  Global->smem staging register-prefetched.
__global__ void __launch_bounds__(256) kD(const float* __restrict__ zw0,
                                          const float* __restrict__ zw1) {
    __shared__ __align__(16) float sA[KC][132];   // [k][128 i + pad]
    __shared__ __align__(16) float sBd[KC][264];  // [k][4 quarters * 64 + pad]
    int i0 = blockIdx.x * 128;
    int tid = threadIdx.x;
    int jg = tid & 15;   // 16 j-groups
    int ig = tid >> 4;   // 16 i-groups x 8 i
    const float* zw = (i0 < B_HALF) ? (zw0 + i0 * 128) : (zw1 + (i0 - B_HALF) * 128);
    float rm[8], rl[8];
#pragma unroll
    for (int r = 0; r < 8; ++r) { rm[r] = -1e30f; rl[r] = 0.f; }
    int js0 = blockIdx.y * (B_TOT / NS);

    // staging indices: 8 elems each for A (16k x 128i) and B (16k x 128j)
    int sk[8], si[8];
#pragma unroll
    for (int u = 0; u < 8; ++u) {
        int idx = tid + u * 256;
        sk[u] = idx & 15;
        si[u] = idx >> 4;
    }
    float a_reg[8], b_reg[8];

    for (int jt = 0; jt < 4; ++jt) {
        int jbase = js0 + jt * 128;
        unsigned long long acc[4][8];
#pragma unroll
        for (int p = 0; p < 4; ++p)
#pragma unroll
            for (int j = 0; j < 8; ++j) acc[p][j] = 0ull;

        // prefetch chunk kc=0
#pragma unroll
        for (int u = 0; u < 8; ++u) a_reg[u] = zw[si[u] * 128 + sk[u]];
#pragma unroll
        for (int u = 0; u < 8; ++u) b_reg[u] = g_pred[(jbase + si[u]) * 128 + sk[u]];

        for (int kc = 0; kc < 128; kc += KC) {
            __syncthreads();
#pragma unroll
            for (int u = 0; u < 8; ++u) sA[sk[u]][si[u]] = a_reg[u];
#pragma unroll
            for (int u = 0; u < 8; ++u) {
                // j = si[u]: quarter = j>>5, pos-in-quarter = j&31 -> 2 floats
                int j = si[u];
                *(float2*)&sBd[sk[u]][(j >> 5) * 64 + 2 * (j & 31)] =
                    make_float2(b_reg[u], b_reg[u]);
            }
            __syncthreads();
            if (kc + KC < 128) {
                int kn = kc + KC;
#pragma unroll
                for (int u = 0; u < 8; ++u) a_reg[u] = zw[si[u] * 128 + kn + sk[u]];
#pragma unroll
                for (int u = 0; u < 8; ++u)
                    b_reg[u] = g_pred[(jbase + si[u]) * 128 + kn + sk[u]];
            }
#pragma unroll
            for (int k = 0; k < KC; ++k) {
                ulonglong2 A0 = *(const ulonglong2*)&sA[k][ig * 8];
                ulonglong2 A1 = *(const ulonglong2*)&sA[k][ig * 8 + 4];
                ulonglong2 Q0 = *(const ulonglong2*)&sBd[k][jg * 4];
                ulonglong2 Q1 = *(const ulonglong2*)&sBd[k][64 + jg * 4];
                ulonglong2 Q2 = *(const ulonglong2*)&sBd[k][128 + jg * 4];
                ulonglong2 Q3 = *(const ulonglong2*)&sBd[k][192 + jg * 4];
                ffma2(acc[0][0], A0.x, Q0.x); ffma2(acc[0][1], A0.x, Q0.y);
                ffma2(acc[0][2], A0.x, Q1.x); ffma2(acc[0][3], A0.x, Q1.y);
                ffma2(acc[0][4], A0.x, Q2.x); ffma2(acc[0][5], A0.x, Q2.y);
                ffma2(acc[0][6], A0.x, Q3.x); ffma2(acc[0][7], A0.x, Q3.y);
                ffma2(acc[1][0], A0.y, Q0.x); ffma2(acc[1][1], A0.y, Q0.y);
                ffma2(acc[1][2], A0.y, Q1.x); ffma2(acc[1][3], A0.y, Q1.y);
                ffma2(acc[1][4], A0.y, Q2.x); ffma2(acc[1][5], A0.y, Q2.y);
                ffma2(acc[1][6], A0.y, Q3.x); ffma2(acc[1][7], A0.y, Q3.y);
                ffma2(acc[2][0], A1.x, Q0.x); ffma2(acc[2][1], A1.x, Q0.y);
                ffma2(acc[2][2], A1.x, Q1.x); ffma2(acc[2][3], A1.x, Q1.y);
                ffma2(acc[2][4], A1.x, Q2.x); ffma2(acc[2][5], A1.x, Q2.y);
                ffma2(acc[2][6], A1.x, Q3.x); ffma2(acc[2][7], A1.x, Q3.y);
                ffma2(acc[3][0], A1.y, Q0.x); ffma2(acc[3][1], A1.y, Q0.y);
                ffma2(acc[3][2], A1.y, Q1.x); ffma2(acc[3][3], A1.y, Q1.y);
                ffma2(acc[3][4], A1.y, Q2.x); ffma2(acc[3][5], A1.y, Q2.y);
                ffma2(acc[3][6], A1.y, Q3.x); ffma2(acc[3][7], A1.y, Q3.y);
            }
        }
        // epilogue: unpack, online LSE, diag capture
        // j_global for acc[.][jj] = jbase + (jj>>1)*32 + 2*jg + (jj&1)
#pragma unroll
        for (int p = 0; p < 4; ++p) {
            float v0[8], v1[8];
#pragma unroll
            for (int jj = 0; jj < 8; ++jj) {
                float2 v = up2(acc[p][jj]);
                v0[jj] = v.x;
                v1[jj] = v.y;
            }
#pragma unroll
            for (int h = 0; h < 2; ++h) {
                int r = 2 * p + h;
                const float* vv = h ? v1 : v0;
                float tmax = vv[0];
#pragma unroll
                for (int jj = 1; jj < 8; ++jj) tmax = fmaxf(tmax, vv[jj]);
                if (tmax > rm[r]) {
                    rl[r] *= __expf(rm[r] - tmax);
                    rm[r] = tmax;
                }
                float add = 0.f;
#pragma unroll
                for (int jj = 0; jj < 8; ++jj) add += __expf(vv[jj] - rm[r]);
                rl[r] += add;
                int irow = i0 + ig * 8 + r;
#pragma unroll
                for (int jj = 0; jj < 8; ++jj) {
                    int jglob = jbase + (jj >> 1) * 32 + 2 * jg + (jj & 1);
                    if (jglob == irow) g_diag[irow] = vv[jj];
                }
            }
        }
    }
    __syncthreads();
    // combine 16 jg-partials per row (reuse smem)
    float* pm = &sBd[0][0];  // [128][16]
    float* pl = &sA[0][0];   // [128][16]
#pragma unroll
    for (int r = 0; r < 8; ++r) {
        int row = ig * 8 + r;
        pm[row * 16 + jg] = rm[r];
        pl[row * 16 + jg] = rl[r];
    }
    __syncthreads();
    if (tid < 128) {
        float m = -1e30f;
#pragma unroll
        for (int t = 0; t < 16; ++t) m = fmaxf(m, pm[tid * 16 + t]);
        float l = 0.f;
#pragma unroll
        for (int t = 0; t < 16; ++t) l += pl[tid * 16 + t] * __expf(pm[tid * 16 + t] - m);
        int irow = i0 + tid;
        g_pm[irow * NS + blockIdx.y] = m;
        g_pl[irow * NS + blockIdx.y] = l;
    }
}

// ---------------- Kernel E ----------------
__global__ void __launch_bounds__(1024) kE(float* out) {
    __shared__ float red[1024];
    int tid = threadIdx.x;
    float local = 0.f;
    for (int i = tid; i < B_TOT; i += 1024) {
        float m = -1e30f;
#pragma unroll
        for (int s = 0; s < NS; ++s) m = fmaxf(m, g_pm[i * NS + s]);
        float l = 0.f;
#pragma unroll
        for (int s = 0; s < NS; ++s) l += g_pl[i * NS + s] * __expf(g_pm[i * NS + s] - m);
        local += (m + logf(l)) - g_diag[i];
    }
    red[tid] = local;
    __syncthreads();
    for (int w = 512; w > 0; w >>= 1) {
        if (tid < w) red[tid] += red[tid + w];
        __syncthreads();
    }
    if (tid == 0) out[0] = red[0] / (float)B_TOT;
}

extern "C" void kernel_launch(void* const* d_in, const int* in_sizes, int n_in,
                              void* d_out, int out_size) {
    const float* zw0   = (const float*)d_in[0];
    const float* zw1   = (const float*)d_in[1];
    const float* c     = (const float*)d_in[2];
    const float* Wk_w  = (const float*)d_in[3];
    const float* Wk_b  = (const float*)d_in[4];
    const float* Ww0_w = (const float*)d_in[5];
    const float* Ww0_b = (const float*)d_in[6];
    const float* Ww1_w = (const float*)d_in[7];
    const float* Ww1_b = (const float*)d_in[8];
    const float* lin0_w = (const float*)d_in[9];
    const float* lin0_b = (const float*)d_in[10];
    const float* lin1_w = (const float*)d_in[11];
    const float* lin1_b = (const float*)d_in[12];
    const float* a01w = (const float*)d_in[13];
    const float* a01b = (const float*)d_in[14];
    const float* a02w = (const float*)d_in[15];
    const float* a02b = (const float*)d_in[16];
    const float* a11w = (const float*)d_in[17];
    const float* a11b = (const float*)d_in[18];
    const float* a12w = (const float*)d_in[19];
    const float* a12b = (const float*)d_in[20];

    kA<<<128, 256>>>(zw0, lin0_w, lin0_b, a01w, a01b, a02w, a02b, 0);
    kA<<<128, 256>>>(zw1, lin1_w, lin1_b, a11w, a11b, a12w, a12b, B_HALF);
    kB<<<2, 256>>>();
    kC<<<dim3(128, 2), 256>>>(c, Wk_w, Wk_b, Ww0_w, Ww0_b, Ww1_w, Ww1_b);
    kD<<<dim3(32, NS), 256>>>(zw0, zw1);
    kE<<<1, 1024>>>((float*)d_out);
}

// round 10
// speedup vs baseline: 2.8699x; 1.3022x over previous
#include <cuda_runtime.h>
#include <cuda_bf16.h>
#include <math.h>
#include <stdint.h>

#define B_TOT 4096
#define B_HALF 2048
#define NS 8
#define SAS 132
#define KTOT 384          // [hi | lo/hi dup] concatenated K
#define KC 64             // k-chunk in kD
#define SBPAD 72          // smem row stride (64 + 8 pad) in bf16

// ---------------- device scratch ----------------
__device__ float g_zt[B_TOT * 64];
__device__ float g_s[B_TOT];
__device__ float g_e[B_TOT];
__device__ float g_S[2];
__device__ float g_P[128];
__device__ float g_pm[B_TOT * NS];
__device__ float g_pl[B_TOT * NS];
__device__ float g_diag[B_TOT];
// A' = [Ah | Al | Ah], B' = [Bh | Bh | Bl] along K (384 cols)
__device__ __align__(16) __nv_bfloat16 g_zwc[B_TOT * KTOT];
__device__ __align__(16) __nv_bfloat16 g_predc[B_TOT * KTOT];

__device__ __forceinline__ uint32_t smem_u32(const void* p) {
    uint32_t a;
    asm("{ .reg .u64 t; cvta.to.shared.u64 t, %1; cvt.u32.u64 %0, t; }"
        : "=r"(a) : "l"(p));
    return a;
}

// ---------------- Kernel A: zt/score + zw bf16 hi/lo emit ----------------
__global__ void __launch_bounds__(256) kA(const float* __restrict__ zw0,
                                          const float* __restrict__ zw1,
                                          const float* __restrict__ lw0,
                                          const float* __restrict__ lb0,
                                          const float* __restrict__ lw1,
                                          const float* __restrict__ lb1,
                                          const float* __restrict__ a1w0,
                                          const float* __restrict__ a1b0,
                                          const float* __restrict__ a2w0,
                                          const float* __restrict__ a2b0,
                                          const float* __restrict__ a1w1,
                                          const float* __restrict__ a1b1,
                                          const float* __restrict__ a2w1,
                                          const float* __restrict__ a2b1) {
    __shared__ float s_zw[16][128];
    __shared__ float s_zt[16][64];
    __shared__ float s_h[16][32];
    int base = blockIdx.x * 16;
    int g = (base >= B_HALF) ? 1 : 0;
    const float* zw = g ? (zw1 - B_HALF * 128) : zw0;
    const float* lw = g ? lw1 : lw0;
    const float* lb = g ? lb1 : lb0;
    const float* a1w = g ? a1w1 : a1w0;
    const float* a1b = g ? a1b1 : a1b0;
    const float* a2w = g ? a2w1 : a2w0;
    const float* a2b = g ? a2b1 : a2b0;
    int tid = threadIdx.x;
    for (int idx = tid; idx < 16 * 128; idx += 256)
        s_zw[idx >> 7][idx & 127] = zw[base * 128 + idx];
    __syncthreads();
    // emit bf16 hi/lo concatenated layout
    for (int idx = tid; idx < 16 * 128; idx += 256) {
        int r = idx >> 7, k = idx & 127;
        float x = s_zw[r][k];
        __nv_bfloat16 h = __float2bfloat16_rn(x);
        __nv_bfloat16 l = __float2bfloat16_rn(x - __bfloat162float(h));
        __nv_bfloat16* dst = &g_zwc[(size_t)(base + r) * KTOT];
        dst[k] = h;
        dst[128 + k] = l;
        dst[256 + k] = h;
    }
    for (int idx = tid; idx < 16 * 64; idx += 256) {
        int r = idx >> 6, k = idx & 63;
        const float* w = lw + k * 128;
        float acc = lb[k];
#pragma unroll 16
        for (int kk = 0; kk < 128; ++kk) acc = fmaf(w[kk], s_zw[r][kk], acc);
        acc = fmaxf(acc, 0.f);
        s_zt[r][k] = acc;
        g_zt[(base + r) * 64 + k] = acc;
    }
    __syncthreads();
    for (int idx = tid; idx < 16 * 32; idx += 256) {
        int r = idx >> 5, u = idx & 31;
        const float* w = a1w + u * 64;
        float acc = a1b[u];
#pragma unroll 16
        for (int kk = 0; kk < 64; ++kk) acc = fmaf(w[kk], s_zt[r][kk], acc);
        s_h[r][u] = tanhf(acc);
    }
    __syncthreads();
    if (tid < 16) {
        float acc = a2b[0];
#pragma unroll
        for (int u = 0; u < 32; ++u) acc = fmaf(a2w[u], s_h[tid][u], acc);
        g_s[base + tid] = acc;
    }
}

// ---------------- Kernel B ----------------
__global__ void __launch_bounds__(256) kB() {
    int g = blockIdx.x;
    int tid = threadIdx.x;
    const float* s = g_s + g * B_HALF;
    __shared__ float red[256];
    __shared__ float red2[4][64];
    float m = -1e30f;
    for (int j = tid; j < B_HALF; j += 256) m = fmaxf(m, s[j]);
    red[tid] = m;
    __syncthreads();
    for (int w = 128; w > 0; w >>= 1) {
        if (tid < w) red[tid] = fmaxf(red[tid], red[tid + w]);
        __syncthreads();
    }
    m = red[0];
    __syncthreads();
    float lsum = 0.f;
    for (int j = tid; j < B_HALF; j += 256) {
        float e = __expf(s[j] - m);
        g_e[g * B_HALF + j] = e;
        lsum += e;
    }
    red[tid] = lsum;
    __syncthreads();
    for (int w = 128; w > 0; w >>= 1) {
        if (tid < w) red[tid] += red[tid + w];
        __syncthreads();
    }
    if (tid == 0) g_S[g] = red[0];
    __syncthreads();
    int k = tid & 63, sl = tid >> 6;
    const float* zt = g_zt + g * B_HALF * 64;
    const float* e = g_e + g * B_HALF;
    float p0 = 0.f, p1 = 0.f;
    int j0 = sl * 512;
#pragma unroll 4
    for (int j = j0; j < j0 + 512; j += 2) {
        p0 = fmaf(e[j], zt[j * 64 + k], p0);
        p1 = fmaf(e[j + 1], zt[(j + 1) * 64 + k], p1);
    }
    red2[sl][k] = p0 + p1;
    __syncthreads();
    if (tid < 64)
        g_P[g * 64 + tid] =
            red2[0][tid] + red2[1][tid] + red2[2][tid] + red2[3][tid];
}

// ---------------- Kernel C: pred GEMM -> bf16 hi/lo concat ----------------
__global__ void __launch_bounds__(256) kC(const float* __restrict__ c,
                                          const float* __restrict__ Wk_w,
                                          const float* __restrict__ Wk_b,
                                          const float* __restrict__ Ww0_w,
                                          const float* __restrict__ Ww0_b,
                                          const float* __restrict__ Ww1_w,
                                          const float* __restrict__ Ww1_b) {
    __shared__ __align__(16) float feat[32][SAS];
    __shared__ __align__(16) float W[64][SAS];
    int r0 = blockIdx.x * 32;
    int c0 = blockIdx.y * 64;
    int g = (r0 >= B_HALF) ? 1 : 0;
    const float* Ww = g ? Ww1_w : Ww0_w;
    const float* Wb = g ? Ww1_b : Ww0_b;
    int tid = threadIdx.x;
    float S = g_S[g];
    const float* P = g_P + g * 64;
    for (int idx = tid; idx < 32 * 128; idx += 256) {
        int r = idx >> 7, k = idx & 127;
        int i = r0 + r;
        float v;
        if (k < 64) {
            float e = g_e[i];
            v = (P[k] - e * g_zt[i * 64 + k]) / (S - e);
        } else {
            v = c[i * 64 + (k - 64)];
        }
        feat[r][k] = v;
    }
    for (int idx = tid; idx < 64 * 128; idx += 256) {
        int o = idx >> 7, k = idx & 127;
        W[o][k] = (k < 64) ? Ww[(c0 + o) * 64 + k] : Wk_w[(c0 + o) * 64 + (k - 64)];
    }
    __syncthreads();
    int tx = tid & 63, ty = tid >> 6;
    float acc[8];
    float b = Wb[c0 + tx] + Wk_b[c0 + tx];
#pragma unroll
    for (int r = 0; r < 8; ++r) acc[r] = b;
#pragma unroll 8
    for (int k4 = 0; k4 < 32; ++k4) {
        float4 w = *(const float4*)&W[tx][k4 * 4];
#pragma unroll
        for (int r = 0; r < 8; ++r) {
            float4 f = *(const float4*)&feat[ty * 8 + r][k4 * 4];
            acc[r] = fmaf(w.x, f.x, acc[r]);
            acc[r] = fmaf(w.y, f.y, acc[r]);
            acc[r] = fmaf(w.z, f.z, acc[r]);
            acc[r] = fmaf(w.w, f.w, acc[r]);
        }
    }
#pragma unroll
    for (int r = 0; r < 8; ++r) {
        int row = r0 + ty * 8 + r;
        float x = acc[r];
        __nv_bfloat16 h = __float2bfloat16_rn(x);
        __nv_bfloat16 l = __float2bfloat16_rn(x - __bfloat162float(h));
        __nv_bfloat16* dst = &g_predc[(size_t)row * KTOT];
        dst[c0 + tx] = h;
        dst[128 + c0 + tx] = h;
        dst[256 + c0 + tx] = l;
    }
}

// ---------------- Kernel D: mma.sync bf16 GEMM (K=384) + online row-LSE ----------------
// grid (32 i-blocks of 128, NS=8 j-splits of 512), 256 threads = 8 warps.
// Warp tile 32i x 32j (warps 4x2). K chunks of 64 staged in smem (pad-72 rows).
__global__ void __launch_bounds__(256) kD() {
    __shared__ __align__(16) __nv_bfloat16 sA[128 * SBPAD];
    __shared__ __align__(16) __nv_bfloat16 sB[64 * SBPAD];
    __shared__ float spm[128][8];
    __shared__ float spl[128][8];
    int tid = threadIdx.x;
    int warp = tid >> 5, lane = tid & 31;
    int wi = warp >> 1, wj = warp & 1;
    int i0 = blockIdx.x * 128;
    int by = blockIdx.y;
    uint32_t sAu = smem_u32(sA), sBu = smem_u32(sB);

    float rm[4], rl[4];
#pragma unroll
    for (int s = 0; s < 4; ++s) { rm[s] = -1e30f; rl[s] = 0.f; }

    for (int jt = 0; jt < 8; ++jt) {
        int jbase = by * 512 + jt * 64;
        float acc[2][4][4];
#pragma unroll
        for (int mf = 0; mf < 2; ++mf)
#pragma unroll
            for (int gg = 0; gg < 4; ++gg)
#pragma unroll
                for (int e = 0; e < 4; ++e) acc[mf][gg][e] = 0.f;

        for (int kc = 0; kc < KTOT; kc += KC) {
            __syncthreads();
            // fill A chunk: 128 rows x 64 cols (8 x 16B per row)
#pragma unroll
            for (int u = 0; u < 4; ++u) {
                int idx = tid + u * 256;
                int r = idx >> 3, ch = idx & 7;
                *(uint4*)&sA[r * SBPAD + ch * 8] =
                    *(const uint4*)&g_zwc[(size_t)(i0 + r) * KTOT + kc + ch * 8];
            }
            // fill B chunk: 64 rows x 64 cols
#pragma unroll
            for (int u = 0; u < 2; ++u) {
                int idx = tid + u * 256;
                int r = idx >> 3, ch = idx & 7;
                *(uint4*)&sB[r * SBPAD + ch * 8] =
                    *(const uint4*)&g_predc[(size_t)(jbase + r) * KTOT + kc + ch * 8];
            }
            __syncthreads();
#pragma unroll
            for (int ks = 0; ks < 4; ++ks) {
                int kk = ks * 16;
                uint32_t a[2][4], bfr[4][2];
#pragma unroll
                for (int mf = 0; mf < 2; ++mf) {
                    uint32_t addr = sAu +
                        (uint32_t)(((wi * 32 + mf * 16 + (lane & 15)) * SBPAD +
                                    kk + (lane >> 4) * 8) * 2);
                    asm volatile(
                        "ldmatrix.sync.aligned.m8n8.x4.shared.b16 "
                        "{%0, %1, %2, %3}, [%4];"
                        : "=r"(a[mf][0]), "=r"(a[mf][1]),
                          "=r"(a[mf][2]), "=r"(a[mf][3])
                        : "r"(addr));
                }
#pragma unroll
                for (int gg = 0; gg < 4; ++gg) {
                    uint32_t addr = sBu +
                        (uint32_t)(((wj * 32 + gg * 8 + (lane & 7)) * SBPAD +
                                    kk + ((lane >> 3) & 1) * 8) * 2);
                    asm volatile(
                        "ldmatrix.sync.aligned.m8n8.x2.shared.b16 "
                        "{%0, %1}, [%2];"
                        : "=r"(bfr[gg][0]), "=r"(bfr[gg][1])
                        : "r"(addr));
                }
#pragma unroll
                for (int mf = 0; mf < 2; ++mf)
#pragma unroll
                    for (int gg = 0; gg < 4; ++gg) {
                        asm volatile(
                            "mma.sync.aligned.m16n8k16.row.col.f32.bf16.bf16.f32 "
                            "{%0, %1, %2, %3}, {%4, %5, %6, %7}, {%8, %9}, "
                            "{%0, %1, %2, %3};"
                            : "+f"(acc[mf][gg][0]), "+f"(acc[mf][gg][1]),
                              "+f"(acc[mf][gg][2]), "+f"(acc[mf][gg][3])
                            : "r"(a[mf][0]), "r"(a[mf][1]),
                              "r"(a[mf][2]), "r"(a[mf][3]),
                              "r"(bfr[gg][0]), "r"(bfr[gg][1]));
                    }
            }
        }
        // epilogue: online LSE per row-slot, diag capture
#pragma unroll
        for (int mf = 0; mf < 2; ++mf)
#pragma unroll
            for (int half = 0; half < 2; ++half) {
                int slot = mf * 2 + half;
                float v[8];
#pragma unroll
                for (int gg = 0; gg < 4; ++gg) {
                    v[gg * 2] = acc[mf][gg][half * 2];
                    v[gg * 2 + 1] = acc[mf][gg][half * 2 + 1];
                }
                float tmax = v[0];
#pragma unroll
                for (int u = 1; u < 8; ++u) tmax = fmaxf(tmax, v[u]);
                if (tmax > rm[slot]) {
                    rl[slot] *= __expf(rm[slot] - tmax);
                    rm[slot] = tmax;
                }
                float add = 0.f;
#pragma unroll
                for (int u = 0; u < 8; ++u) add += __expf(v[u] - rm[slot]);
                rl[slot] += add;
                int irow = i0 + wi * 32 + mf * 16 + half * 8 + (lane >> 2);
#pragma unroll
                for (int gg = 0; gg < 4; ++gg)
#pragma unroll
                    for (int e = 0; e < 2; ++e) {
                        int j = jbase + wj * 32 + gg * 8 + (lane & 3) * 2 + e;
                        if (j == irow) g_diag[irow] = v[gg * 2 + e];
                    }
            }
    }
    __syncthreads();
    // merge 8 partials per row
#pragma unroll
    for (int mf = 0; mf < 2; ++mf)
#pragma unroll
        for (int half = 0; half < 2; ++half) {
            int slot = mf * 2 + half;
            int row = wi * 32 + mf * 16 + half * 8 + (lane >> 2);
            int col = wj * 4 + (lane & 3);
            spm[row][col] = rm[slot];
            spl[row][col] = rl[slot];
        }
    __syncthreads();
    if (tid < 128) {
        float m = -1e30f;
#pragma unroll
        for (int t = 0; t < 8; ++t) m = fmaxf(m, spm[tid][t]);
        float l = 0.f;
#pragma unroll
        for (int t = 0; t < 8; ++t) l += spl[tid][t] * __expf(spm[tid][t] - m);
        int irow = i0 + tid;
        g_pm[irow * NS + by] = m;
        g_pl[irow * NS + by] = l;
    }
}

// ---------------- Kernel E ----------------
__global__ void __launch_bounds__(1024) kE(float* out) {
    __shared__ float red[1024];
    int tid = threadIdx.x;
    float local = 0.f;
    for (int i = tid; i < B_TOT; i += 1024) {
        float m = -1e30f;
#pragma unroll
        for (int s = 0; s < NS; ++s) m = fmaxf(m, g_pm[i * NS + s]);
        float l = 0.f;
#pragma unroll
        for (int s = 0; s < NS; ++s) l += g_pl[i * NS + s] * __expf(g_pm[i * NS + s] - m);
        local += (m + logf(l)) - g_diag[i];
    }
    red[tid] = local;
    __syncthreads();
    for (int w = 512; w > 0; w >>= 1) {
        if (tid < w) red[tid] += red[tid + w];
        __syncthreads();
    }
    if (tid == 0) out[0] = red[0] / (float)B_TOT;
}

extern "C" void kernel_launch(void* const* d_in, const int* in_sizes, int n_in,
                              void* d_out, int out_size) {
    const float* zw0   = (const float*)d_in[0];
    const float* zw1   = (const float*)d_in[1];
    const float* c     = (const float*)d_in[2];
    const float* Wk_w  = (const float*)d_in[3];
    const float* Wk_b  = (const float*)d_in[4];
    const float* Ww0_w = (const float*)d_in[5];
    const float* Ww0_b = (const float*)d_in[6];
    const float* Ww1_w = (const float*)d_in[7];
    const float* Ww1_b = (const float*)d_in[8];
    const float* lin0_w = (const float*)d_in[9];
    const float* lin0_b = (const float*)d_in[10];
    const float* lin1_w = (const float*)d_in[11];
    const float* lin1_b = (const float*)d_in[12];
    const float* a01w = (const float*)d_in[13];
    const float* a01b = (const float*)d_in[14];
    const float* a02w = (const float*)d_in[15];
    const float* a02b = (const float*)d_in[16];
    const float* a11w = (const float*)d_in[17];
    const float* a11b = (const float*)d_in[18];
    const float* a12w = (const float*)d_in[19];
    const float* a12b = (const float*)d_in[20];

    kA<<<256, 256>>>(zw0, zw1, lin0_w, lin0_b, lin1_w, lin1_b,
                     a01w, a01b, a02w, a02b, a11w, a11b, a12w, a12b);
    kB<<<2, 256>>>();
    kC<<<dim3(128, 2), 256>>>(c, Wk_w, Wk_b, Ww0_w, Ww0_b, Ww1_w, Ww1_b);
    kD<<<dim3(32, NS), 256>>>();
    kE<<<1, 1024>>>((float*)d_out);
}

// round 16
// speedup vs baseline: 7.5990x; 2.6479x over previous
#include <cuda_runtime.h>
#include <cuda_bf16.h>
#include <math.h>
#include <stdint.h>

#define B_TOT 4096
#define B_HALF 2048
#define NS 8
#define SAS 132
#define KTOT 384
#define KC 64
#define SBPAD 72

// ---------------- device scratch ----------------
__device__ float g_zt[B_TOT * 64];
__device__ float g_s[B_TOT];
__device__ float g_e[B_TOT];
__device__ float g_m[2];
__device__ float g_S[2];
__device__ float g_P[128];
__device__ float g_Sp[32];
__device__ float g_Pp[32 * 64];
__device__ float g_pm[B_TOT * NS];
__device__ float g_pl[B_TOT * NS];
__device__ float g_diag[B_TOT];
__device__ __align__(16) __nv_bfloat16 g_zwc[B_TOT * KTOT];
__device__ __align__(16) __nv_bfloat16 g_predc[B_TOT * KTOT];

__device__ __forceinline__ uint32_t smem_u32(const void* p) {
    uint32_t a;
    asm("{ .reg .u64 t; cvta.to.shared.u64 t, %1; cvt.u32.u64 %0, t; }"
        : "=r"(a) : "l"(p));
    return a;
}

// ---------------- kA1: zt = relu(zw@lwT+lb) tiled GEMM + zw bf16 concat emit ----------------
__global__ void __launch_bounds__(256) kA1(const float* __restrict__ zw0,
                                           const float* __restrict__ zw1,
                                           const float* __restrict__ lw0,
                                           const float* __restrict__ lb0,
                                           const float* __restrict__ lw1,
                                           const float* __restrict__ lb1) {
    __shared__ __align__(16) float feat[32][SAS];
    __shared__ __align__(16) float W[64][SAS];
    int r0 = blockIdx.x * 32;
    int g = (r0 >= B_HALF) ? 1 : 0;
    const float* zw = g ? (zw1 + (r0 - B_HALF) * 128) : (zw0 + r0 * 128);
    const float* lw = g ? lw1 : lw0;
    const float* lb = g ? lb1 : lb0;
    int tid = threadIdx.x;
    for (int idx = tid; idx < 32 * 128; idx += 256)
        feat[idx >> 7][idx & 127] = zw[idx];
    for (int idx = tid; idx < 64 * 128; idx += 256)
        W[idx >> 7][idx & 127] = lw[idx];
    __syncthreads();
    for (int idx = tid; idx < 32 * 128; idx += 256) {
        int r = idx >> 7, k = idx & 127;
        float x = feat[r][k];
        __nv_bfloat16 h = __float2bfloat16_rn(x);
        __nv_bfloat16 l = __float2bfloat16_rn(x - __bfloat162float(h));
        __nv_bfloat16* dst = &g_zwc[(size_t)(r0 + r) * KTOT];
        dst[k] = h;
        dst[128 + k] = l;
        dst[256 + k] = h;
    }
    int tx = tid & 63, ty = tid >> 6;
    float acc[8];
    float b = lb[tx];
#pragma unroll
    for (int r = 0; r < 8; ++r) acc[r] = b;
#pragma unroll 8
    for (int k4 = 0; k4 < 32; ++k4) {
        float4 w = *(const float4*)&W[tx][k4 * 4];
#pragma unroll
        for (int r = 0; r < 8; ++r) {
            float4 f = *(const float4*)&feat[ty * 8 + r][k4 * 4];
            acc[r] = fmaf(w.x, f.x, acc[r]);
            acc[r] = fmaf(w.y, f.y, acc[r]);
            acc[r] = fmaf(w.z, f.z, acc[r]);
            acc[r] = fmaf(w.w, f.w, acc[r]);
        }
    }
#pragma unroll
    for (int r = 0; r < 8; ++r)
        g_zt[(r0 + ty * 8 + r) * 64 + tx] = fmaxf(acc[r], 0.f);
}

// ---------------- kA2: attention scores ----------------
__global__ void __launch_bounds__(256) kA2(const float* __restrict__ a1w0,
                                           const float* __restrict__ a1b0,
                                           const float* __restrict__ a2w0,
                                           const float* __restrict__ a2b0,
                                           const float* __restrict__ a1w1,
                                           const float* __restrict__ a1b1,
                                           const float* __restrict__ a2w1,
                                           const float* __restrict__ a2b1) {
    __shared__ float zt_s[32][68];
    __shared__ float a1wT[64][33];
    __shared__ float sh[32][36];
    int r0 = blockIdx.x * 32;
    int g = (r0 >= B_HALF) ? 1 : 0;
    const float* a1w = g ? a1w1 : a1w0;
    const float* a1b = g ? a1b1 : a1b0;
    const float* a2w = g ? a2w1 : a2w0;
    const float* a2b = g ? a2b1 : a2b0;
    int tid = threadIdx.x;
    for (int idx = tid; idx < 32 * 64; idx += 256)
        zt_s[idx >> 6][idx & 63] = g_zt[(r0 + (idx >> 6)) * 64 + (idx & 63)];
    for (int idx = tid; idx < 32 * 64; idx += 256) {
        int u = idx >> 6, kk = idx & 63;
        a1wT[kk][u] = a1w[u * 64 + kk];
    }
    __syncthreads();
    int r = tid >> 3, ug = tid & 7;
#pragma unroll
    for (int j = 0; j < 4; ++j) {
        int u = ug * 4 + j;
        float acc = a1b[u];
#pragma unroll 16
        for (int kk = 0; kk < 64; ++kk)
            acc = fmaf(a1wT[kk][u], zt_s[r][kk], acc);
        sh[r][u] = tanhf(acc);
    }
    __syncthreads();
    if (tid < 32) {
        float acc = a2b[0];
#pragma unroll
        for (int u = 0; u < 32; ++u) acc = fmaf(a2w[u], sh[tid][u], acc);
        g_s[r0 + tid] = acc;
    }
}

// ---------------- kB0: per-group max ----------------
__global__ void __launch_bounds__(256) kB0() {
    int g = blockIdx.x;
    int tid = threadIdx.x;
    const float* s = g_s + g * B_HALF;
    __shared__ float red[256];
    float m = -1e30f;
    for (int j = tid; j < B_HALF; j += 256) m = fmaxf(m, s[j]);
    red[tid] = m;
    __syncthreads();
    for (int w = 128; w > 0; w >>= 1) {
        if (tid < w) red[tid] = fmaxf(red[tid], red[tid + w]);
        __syncthreads();
    }
    if (tid == 0) g_m[g] = red[0];
}

// ---------------- kB1: e + partial S/P over 128-row slices ----------------
__global__ void __launch_bounds__(256) kB1() {
    int slice = blockIdx.x, g = blockIdx.y;
    int j0 = g * B_HALF + slice * 128;
    int tid = threadIdx.x;
    __shared__ float se[128];
    __shared__ float red[128];
    __shared__ float red2[4][64];
    float m = g_m[g];
    if (tid < 128) {
        float e = __expf(g_s[j0 + tid] - m);
        g_e[j0 + tid] = e;
        se[tid] = e;
    }
    __syncthreads();
    if (tid < 128) red[tid] = se[tid];
    __syncthreads();
    for (int w = 64; w > 0; w >>= 1) {
        if (tid < w) red[tid] += red[tid + w];
        __syncthreads();
    }
    if (tid == 0) g_Sp[g * 16 + slice] = red[0];
    int k = tid & 63, sl = tid >> 6;
    float p = 0.f;
#pragma unroll 8
    for (int j = sl * 32; j < sl * 32 + 32; ++j)
        p = fmaf(se[j], g_zt[(j0 + j) * 64 + k], p);
    red2[sl][k] = p;
    __syncthreads();
    if (tid < 64)
        g_Pp[(g * 16 + slice) * 64 + tid] =
            red2[0][tid] + red2[1][tid] + red2[2][tid] + red2[3][tid];
}

// ---------------- kB2: combine partials ----------------
__global__ void __launch_bounds__(64) kB2() {
    int g = blockIdx.x;
    int tid = threadIdx.x;
    float p = 0.f;
#pragma unroll
    for (int t = 0; t < 16; ++t) p += g_Pp[(g * 16 + t) * 64 + tid];
    g_P[g * 64 + tid] = p;
    if (tid == 0) {
        float s = 0.f;
#pragma unroll
        for (int t = 0; t < 16; ++t) s += g_Sp[g * 16 + t];
        g_S[g] = s;
    }
}

// ---------------- kC: pred GEMM -> bf16 concat ----------------
__global__ void __launch_bounds__(256) kC(const float* __restrict__ c,
                                          const float* __restrict__ Wk_w,
                                          const float* __restrict__ Wk_b,
                                          const float* __restrict__ Ww0_w,
                                          const float* __restrict__ Ww0_b,
                                          const float* __restrict__ Ww1_w,
                                          const float* __restrict__ Ww1_b) {
    __shared__ __align__(16) float feat[32][SAS];
    __shared__ __align__(16) float W[64][SAS];
    int r0 = blockIdx.x * 32;
    int c0 = blockIdx.y * 64;
    int g = (r0 >= B_HALF) ? 1 : 0;
    const float* Ww = g ? Ww1_w : Ww0_w;
    const float* Wb = g ? Ww1_b : Ww0_b;
    int tid = threadIdx.x;
    float S = g_S[g];
    const float* P = g_P + g * 64;
    for (int idx = tid; idx < 32 * 128; idx += 256) {
        int r = idx >> 7, k = idx & 127;
        int i = r0 + r;
        float v;
        if (k < 64) {
            float e = g_e[i];
            v = (P[k] - e * g_zt[i * 64 + k]) / (S - e);
        } else {
            v = c[i * 64 + (k - 64)];
        }
        feat[r][k] = v;
    }
    for (int idx = tid; idx < 64 * 128; idx += 256) {
        int o = idx >> 7, k = idx & 127;
        W[o][k] = (k < 64) ? Ww[(c0 + o) * 64 + k] : Wk_w[(c0 + o) * 64 + (k - 64)];
    }
    __syncthreads();
    int tx = tid & 63, ty = tid >> 6;
    float acc[8];
    float b = Wb[c0 + tx] + Wk_b[c0 + tx];
#pragma unroll
    for (int r = 0; r < 8; ++r) acc[r] = b;
#pragma unroll 8
    for (int k4 = 0; k4 < 32; ++k4) {
        float4 w = *(const float4*)&W[tx][k4 * 4];
#pragma unroll
        for (int r = 0; r < 8; ++r) {
            float4 f = *(const float4*)&feat[ty * 8 + r][k4 * 4];
            acc[r] = fmaf(w.x, f.x, acc[r]);
            acc[r] = fmaf(w.y, f.y, acc[r]);
            acc[r] = fmaf(w.z, f.z, acc[r]);
            acc[r] = fmaf(w.w, f.w, acc[r]);
        }
    }
#pragma unroll
    for (int r = 0; r < 8; ++r) {
        int row = r0 + ty * 8 + r;
        float x = acc[r];
        __nv_bfloat16 h = __float2bfloat16_rn(x);
        __nv_bfloat16 l = __float2bfloat16_rn(x - __bfloat162float(h));
        __nv_bfloat16* dst = &g_predc[(size_t)row * KTOT];
        dst[c0 + tx] = h;
        dst[128 + c0 + tx] = h;
        dst[256 + c0 + tx] = l;
    }
}

// ---------------- kD: mma.sync bf16 GEMM (K=384) + online row-LSE ----------------
// Register-prefetched staging: next chunk's LDGs issue before the compute phase.
__global__ void __launch_bounds__(256) kD() {
    __shared__ __align__(16) __nv_bfloat16 sA[128 * SBPAD];
    __shared__ __align__(16) __nv_bfloat16 sB[64 * SBPAD];
    __shared__ float spm[128][8];
    __shared__ float spl[128][8];
    int tid = threadIdx.x;
    int warp = tid >> 5, lane = tid & 31;
    int wi = warp >> 1, wj = warp & 1;
    int i0 = blockIdx.x * 128;
    int by = blockIdx.y;
    uint32_t sAu = smem_u32(sA), sBu = smem_u32(sB);

    int ra[4], ca[4], rb[2], cb[2];
#pragma unroll
    for (int u = 0; u < 4; ++u) {
        int idx = tid + u * 256;
        ra[u] = idx >> 3;
        ca[u] = idx & 7;
    }
#pragma unroll
    for (int u = 0; u < 2; ++u) {
        int idx = tid + u * 256;
        rb[u] = idx >> 3;
        cb[u] = idx & 7;
    }

    float rm[4], rl[4];
#pragma unroll
    for (int s = 0; s < 4; ++s) { rm[s] = -1e30f; rl[s] = 0.f; }

    for (int jt = 0; jt < 8; ++jt) {
        int jbase = by * 512 + jt * 64;
        float acc[2][4][4];
#pragma unroll
        for (int mf = 0; mf < 2; ++mf)
#pragma unroll
            for (int gg = 0; gg < 4; ++gg)
#pragma unroll
                for (int e = 0; e < 4; ++e) acc[mf][gg][e] = 0.f;

        uint4 pa[4], pb[2];
#pragma unroll
        for (int u = 0; u < 4; ++u)
            pa[u] = *(const uint4*)&g_zwc[(size_t)(i0 + ra[u]) * KTOT + ca[u] * 8];
#pragma unroll
        for (int u = 0; u < 2; ++u)
            pb[u] = *(const uint4*)&g_predc[(size_t)(jbase + rb[u]) * KTOT + cb[u] * 8];

        for (int kc = 0; kc < KTOT; kc += KC) {
            __syncthreads();
#pragma unroll
            for (int u = 0; u < 4; ++u)
                *(uint4*)&sA[ra[u] * SBPAD + ca[u] * 8] = pa[u];
#pragma unroll
            for (int u = 0; u < 2; ++u)
                *(uint4*)&sB[rb[u] * SBPAD + cb[u] * 8] = pb[u];
            __syncthreads();
            if (kc + KC < KTOT) {
                int kn = kc + KC;
#pragma unroll
                for (int u = 0; u < 4; ++u)
                    pa[u] = *(const uint4*)&g_zwc[(size_t)(i0 + ra[u]) * KTOT + kn + ca[u] * 8];
#pragma unroll
                for (int u = 0; u < 2; ++u)
                    pb[u] = *(const uint4*)&g_predc[(size_t)(jbase + rb[u]) * KTOT + kn + cb[u] * 8];
            }
#pragma unroll
            for (int ks = 0; ks < 4; ++ks) {
                int kk = ks * 16;
                uint32_t a[2][4], bfr[4][2];
#pragma unroll
                for (int mf = 0; mf < 2; ++mf) {
                    uint32_t addr = sAu +
                        (uint32_t)(((wi * 32 + mf * 16 + (lane & 15)) * SBPAD +
                                    kk + (lane >> 4) * 8) * 2);
                    asm volatile(
                        "ldmatrix.sync.aligned.m8n8.x4.shared.b16 "
                        "{%0, %1, %2, %3}, [%4];"
                        : "=r"(a[mf][0]), "=r"(a[mf][1]),
                          "=r"(a[mf][2]), "=r"(a[mf][3])
                        : "r"(addr));
                }
#pragma unroll
                for (int gg = 0; gg < 4; ++gg) {
                    uint32_t addr = sBu +
                        (uint32_t)(((wj * 32 + gg * 8 + (lane & 7)) * SBPAD +
                                    kk + ((lane >> 3) & 1) * 8) * 2);
                    asm volatile(
                        "ldmatrix.sync.aligned.m8n8.x2.shared.b16 "
                        "{%0, %1}, [%2];"
                        : "=r"(bfr[gg][0]), "=r"(bfr[gg][1])
                        : "r"(addr));
                }
#pragma unroll
                for (int mf = 0; mf < 2; ++mf)
#pragma unroll
                    for (int gg = 0; gg < 4; ++gg) {
                        asm volatile(
                            "mma.sync.aligned.m16n8k16.row.col.f32.bf16.bf16.f32 "
                            "{%0, %1, %2, %3}, {%4, %5, %6, %7}, {%8, %9}, "
                            "{%0, %1, %2, %3};"
                            : "+f"(acc[mf][gg][0]), "+f"(acc[mf][gg][1]),
                              "+f"(acc[mf][gg][2]), "+f"(acc[mf][gg][3])
                            : "r"(a[mf][0]), "r"(a[mf][1]),
                              "r"(a[mf][2]), "r"(a[mf][3]),
                              "r"(bfr[gg][0]), "r"(bfr[gg][1]));
                    }
            }
        }
#pragma unroll
        for (int mf = 0; mf < 2; ++mf)
#pragma unroll
            for (int half = 0; half < 2; ++half) {
                int slot = mf * 2 + half;
                float v[8];
#pragma unroll
                for (int gg = 0; gg < 4; ++gg) {
                    v[gg * 2] = acc[mf][gg][half * 2];
                    v[gg * 2 + 1] = acc[mf][gg][half * 2 + 1];
                }
                float tmax = v[0];
#pragma unroll
                for (int u = 1; u < 8; ++u) tmax = fmaxf(tmax, v[u]);
                if (tmax > rm[slot]) {
                    rl[slot] *= __expf(rm[slot] - tmax);
                    rm[slot] = tmax;
                }
                float add = 0.f;
#pragma unroll
                for (int u = 0; u < 8; ++u) add += __expf(v[u] - rm[slot]);
                rl[slot] += add;
                int irow = i0 + wi * 32 + mf * 16 + half * 8 + (lane >> 2);
#pragma unroll
                for (int gg = 0; gg < 4; ++gg)
#pragma unroll
                    for (int e = 0; e < 2; ++e) {
                        int j = jbase + wj * 32 + gg * 8 + (lane & 3) * 2 + e;
                        if (j == irow) g_diag[irow] = v[gg * 2 + e];
                    }
            }
    }
    __syncthreads();
#pragma unroll
    for (int mf = 0; mf < 2; ++mf)
#pragma unroll
        for (int half = 0; half < 2; ++half) {
            int slot = mf * 2 + half;
            int row = wi * 32 + mf * 16 + half * 8 + (lane >> 2);
            int col = wj * 4 + (lane & 3);
            spm[row][col] = rm[slot];
            spl[row][col] = rl[slot];
        }
    __syncthreads();
    if (tid < 128) {
        float m = -1e30f;
#pragma unroll
        for (int t = 0; t < 8; ++t) m = fmaxf(m, spm[tid][t]);
        float l = 0.f;
#pragma unroll
        for (int t = 0; t < 8; ++t) l += spl[tid][t] * __expf(spm[tid][t] - m);
        int irow = i0 + tid;
        g_pm[irow * NS + by] = m;
        g_pl[irow * NS + by] = l;
    }
}

// ---------------- kE ----------------
__global__ void __launch_bounds__(1024) kE(float* out) {
    __shared__ float red[1024];
    int tid = threadIdx.x;
    float local = 0.f;
    for (int i = tid; i < B_TOT; i += 1024) {
        float m = -1e30f;
#pragma unroll
        for (int s = 0; s < NS; ++s) m = fmaxf(m, g_pm[i * NS + s]);
        float l = 0.f;
#pragma unroll
        for (int s = 0; s < NS; ++s) l += g_pl[i * NS + s] * __expf(g_pm[i * NS + s] - m);
        local += (m + logf(l)) - g_diag[i];
    }
    red[tid] = local;
    __syncthreads();
    for (int w = 512; w > 0; w >>= 1) {
        if (tid < w) red[tid] += red[tid + w];
        __syncthreads();
    }
    if (tid == 0) out[0] = red[0] / (float)B_TOT;
}

extern "C" void kernel_launch(void* const* d_in, const int* in_sizes, int n_in,
                              void* d_out, int out_size) {
    const float* zw0   = (const float*)d_in[0];
    const float* zw1   = (const float*)d_in[1];
    const float* c     = (const float*)d_in[2];
    const float* Wk_w  = (const float*)d_in[3];
    const float* Wk_b  = (const float*)d_in[4];
    const float* Ww0_w = (const float*)d_in[5];
    const float* Ww0_b = (const float*)d_in[6];
    const float* Ww1_w = (const float*)d_in[7];
    const float* Ww1_b = (const float*)d_in[8];
    const float* lin0_w = (const float*)d_in[9];
    const float* lin0_b = (const float*)d_in[10];
    const float* lin1_w = (const float*)d_in[11];
    const float* lin1_b = (const float*)d_in[12];
    const float* a01w = (const float*)d_in[13];
    const float* a01b = (const float*)d_in[14];
    const float* a02w = (const float*)d_in[15];
    const float* a02b = (const float*)d_in[16];
    const float* a11w = (const float*)d_in[17];
    const float* a11b = (const float*)d_in[18];
    const float* a12w = (const float*)d_in[19];
    const float* a12b = (const float*)d_in[20];

    kA1<<<128, 256>>>(zw0, zw1, lin0_w, lin0_b, lin1_w, lin1_b);
    kA2<<<128, 256>>>(a01w, a01b, a02w, a02b, a11w, a11b, a12w, a12b);
    kB0<<<2, 256>>>();
    kB1<<<dim3(16, 2), 256>>>();
    kB2<<<2, 64>>>();
    kC<<<dim3(128, 2), 256>>>(c, Wk_w, Wk_b, Ww0_w, Ww0_b, Ww1_w, Ww1_b);
    kD<<<dim3(32, NS), 256>>>();
    kE<<<1, 1024>>>((float*)d_out);
}

// round 17
// speedup vs baseline: 8.0802x; 1.0633x over previous
#include <cuda_runtime.h>
#include <cuda_bf16.h>
#include <math.h>
#include <stdint.h>

#define B_TOT 4096
#define B_HALF 2048
#define NS 4
#define SAS 132
#define KTOT 384
#define KC 64
#define SBPAD 72

// ---------------- device scratch ----------------
__device__ float g_zt[B_TOT * 64];
__device__ float g_s[B_TOT];
__device__ float g_e[B_TOT];
__device__ float g_m[2];
__device__ float g_S[2];
__device__ float g_P[128];
__device__ float g_Sp[32];
__device__ float g_Pp[32 * 64];
__device__ float g_pm[B_TOT * NS];
__device__ float g_pl[B_TOT * NS];
__device__ float g_diag[B_TOT];
__device__ __align__(16) __nv_bfloat16 g_zwc[B_TOT * KTOT];
__device__ __align__(16) __nv_bfloat16 g_predc[B_TOT * KTOT];

__device__ __forceinline__ uint32_t smem_u32(const void* p) {
    uint32_t a;
    asm("{ .reg .u64 t; cvta.to.shared.u64 t, %1; cvt.u32.u64 %0, t; }"
        : "=r"(a) : "l"(p));
    return a;
}

// ---------------- kA1: zt = relu(zw@lwT+lb) tiled GEMM + zw bf16 concat emit ----------------
__global__ void __launch_bounds__(256) kA1(const float* __restrict__ zw0,
                                           const float* __restrict__ zw1,
                                           const float* __restrict__ lw0,
                                           const float* __restrict__ lb0,
                                           const float* __restrict__ lw1,
                                           const float* __restrict__ lb1) {
    __shared__ __align__(16) float feat[32][SAS];
    __shared__ __align__(16) float W[64][SAS];
    int r0 = blockIdx.x * 32;
    int g = (r0 >= B_HALF) ? 1 : 0;
    const float* zw = g ? (zw1 + (r0 - B_HALF) * 128) : (zw0 + r0 * 128);
    const float* lw = g ? lw1 : lw0;
    const float* lb = g ? lb1 : lb0;
    int tid = threadIdx.x;
    for (int idx = tid; idx < 32 * 128; idx += 256)
        feat[idx >> 7][idx & 127] = zw[idx];
    for (int idx = tid; idx < 64 * 128; idx += 256)
        W[idx >> 7][idx & 127] = lw[idx];
    __syncthreads();
    for (int idx = tid; idx < 32 * 128; idx += 256) {
        int r = idx >> 7, k = idx & 127;
        float x = feat[r][k];
        __nv_bfloat16 h = __float2bfloat16_rn(x);
        __nv_bfloat16 l = __float2bfloat16_rn(x - __bfloat162float(h));
        __nv_bfloat16* dst = &g_zwc[(size_t)(r0 + r) * KTOT];
        dst[k] = h;
        dst[128 + k] = l;
        dst[256 + k] = h;
    }
    int tx = tid & 63, ty = tid >> 6;
    float acc[8];
    float b = lb[tx];
#pragma unroll
    for (int r = 0; r < 8; ++r) acc[r] = b;
#pragma unroll 8
    for (int k4 = 0; k4 < 32; ++k4) {
        float4 w = *(const float4*)&W[tx][k4 * 4];
#pragma unroll
        for (int r = 0; r < 8; ++r) {
            float4 f = *(const float4*)&feat[ty * 8 + r][k4 * 4];
            acc[r] = fmaf(w.x, f.x, acc[r]);
            acc[r] = fmaf(w.y, f.y, acc[r]);
            acc[r] = fmaf(w.z, f.z, acc[r]);
            acc[r] = fmaf(w.w, f.w, acc[r]);
        }
    }
#pragma unroll
    for (int r = 0; r < 8; ++r)
        g_zt[(r0 + ty * 8 + r) * 64 + tx] = fmaxf(acc[r], 0.f);
}

// ---------------- kA2: attention scores ----------------
__global__ void __launch_bounds__(256) kA2(const float* __restrict__ a1w0,
                                           const float* __restrict__ a1b0,
                                           const float* __restrict__ a2w0,
                                           const float* __restrict__ a2b0,
                                           const float* __restrict__ a1w1,
                                           const float* __restrict__ a1b1,
                                           const float* __restrict__ a2w1,
                                           const float* __restrict__ a2b1) {
    __shared__ float zt_s[32][68];
    __shared__ float a1wT[64][33];
    __shared__ float sh[32][36];
    int r0 = blockIdx.x * 32;
    int g = (r0 >= B_HALF) ? 1 : 0;
    const float* a1w = g ? a1w1 : a1w0;
    const float* a1b = g ? a1b1 : a1b0;
    const float* a2w = g ? a2w1 : a2w0;
    const float* a2b = g ? a2b1 : a2b0;
    int tid = threadIdx.x;
    for (int idx = tid; idx < 32 * 64; idx += 256)
        zt_s[idx >> 6][idx & 63] = g_zt[(r0 + (idx >> 6)) * 64 + (idx & 63)];
    for (int idx = tid; idx < 32 * 64; idx += 256) {
        int u = idx >> 6, kk = idx & 63;
        a1wT[kk][u] = a1w[u * 64 + kk];
    }
    __syncthreads();
    int r = tid >> 3, ug = tid & 7;
#pragma unroll
    for (int j = 0; j < 4; ++j) {
        int u = ug * 4 + j;
        float acc = a1b[u];
#pragma unroll 16
        for (int kk = 0; kk < 64; ++kk)
            acc = fmaf(a1wT[kk][u], zt_s[r][kk], acc);
        sh[r][u] = tanhf(acc);
    }
    __syncthreads();
    if (tid < 32) {
        float acc = a2b[0];
#pragma unroll
        for (int u = 0; u < 32; ++u) acc = fmaf(a2w[u], sh[tid][u], acc);
        g_s[r0 + tid] = acc;
    }
}

// ---------------- kB0: per-group max ----------------
__global__ void __launch_bounds__(256) kB0() {
    int g = blockIdx.x;
    int tid = threadIdx.x;
    const float* s = g_s + g * B_HALF;
    __shared__ float red[256];
    float m = -1e30f;
    for (int j = tid; j < B_HALF; j += 256) m = fmaxf(m, s[j]);
    red[tid] = m;
    __syncthreads();
    for (int w = 128; w > 0; w >>= 1) {
        if (tid < w) red[tid] = fmaxf(red[tid], red[tid + w]);
        __syncthreads();
    }
    if (tid == 0) g_m[g] = red[0];
}

// ---------------- kB1: e + partial S/P over 128-row slices ----------------
__global__ void __launch_bounds__(256) kB1() {
    int slice = blockIdx.x, g = blockIdx.y;
    int j0 = g * B_HALF + slice * 128;
    int tid = threadIdx.x;
    __shared__ float se[128];
    __shared__ float red[128];
    __shared__ float red2[4][64];
    float m = g_m[g];
    if (tid < 128) {
        float e = __expf(g_s[j0 + tid] - m);
        g_e[j0 + tid] = e;
        se[tid] = e;
    }
    __syncthreads();
    if (tid < 128) red[tid] = se[tid];
    __syncthreads();
    for (int w = 64; w > 0; w >>= 1) {
        if (tid < w) red[tid] += red[tid + w];
        __syncthreads();
    }
    if (tid == 0) g_Sp[g * 16 + slice] = red[0];
    int k = tid & 63, sl = tid >> 6;
    float p = 0.f;
#pragma unroll 8
    for (int j = sl * 32; j < sl * 32 + 32; ++j)
        p = fmaf(se[j], g_zt[(j0 + j) * 64 + k], p);
    red2[sl][k] = p;
    __syncthreads();
    if (tid < 64)
        g_Pp[(g * 16 + slice) * 64 + tid] =
            red2[0][tid] + red2[1][tid] + red2[2][tid] + red2[3][tid];
}

// ---------------- kB2: combine partials ----------------
__global__ void __launch_bounds__(64) kB2() {
    int g = blockIdx.x;
    int tid = threadIdx.x;
    float p = 0.f;
#pragma unroll
    for (int t = 0; t < 16; ++t) p += g_Pp[(g * 16 + t) * 64 + tid];
    g_P[g * 64 + tid] = p;
    if (tid == 0) {
        float s = 0.f;
#pragma unroll
        for (int t = 0; t < 16; ++t) s += g_Sp[g * 16 + t];
        g_S[g] = s;
    }
}

// ---------------- kC: pred GEMM -> bf16 concat ----------------
__global__ void __launch_bounds__(256) kC(const float* __restrict__ c,
                                          const float* __restrict__ Wk_w,
                                          const float* __restrict__ Wk_b,
                                          const float* __restrict__ Ww0_w,
                                          const float* __restrict__ Ww0_b,
                                          const float* __restrict__ Ww1_w,
                                          const float* __restrict__ Ww1_b) {
    __shared__ __align__(16) float feat[32][SAS];
    __shared__ __align__(16) float W[64][SAS];
    int r0 = blockIdx.x * 32;
    int c0 = blockIdx.y * 64;
    int g = (r0 >= B_HALF) ? 1 : 0;
    const float* Ww = g ? Ww1_w : Ww0_w;
    const float* Wb = g ? Ww1_b : Ww0_b;
    int tid = threadIdx.x;
    float S = g_S[g];
    const float* P = g_P + g * 64;
    for (int idx = tid; idx < 32 * 128; idx += 256) {
        int r = idx >> 7, k = idx & 127;
        int i = r0 + r;
        float v;
        if (k < 64) {
            float e = g_e[i];
            v = (P[k] - e * g_zt[i * 64 + k]) / (S - e);
        } else {
            v = c[i * 64 + (k - 64)];
        }
        feat[r][k] = v;
    }
    for (int idx = tid; idx < 64 * 128; idx += 256) {
        int o = idx >> 7, k = idx & 127;
        W[o][k] = (k < 64) ? Ww[(c0 + o) * 64 + k] : Wk_w[(c0 + o) * 64 + (k - 64)];
    }
    __syncthreads();
    int tx = tid & 63, ty = tid >> 6;
    float acc[8];
    float b = Wb[c0 + tx] + Wk_b[c0 + tx];
#pragma unroll
    for (int r = 0; r < 8; ++r) acc[r] = b;
#pragma unroll 8
    for (int k4 = 0; k4 < 32; ++k4) {
        float4 w = *(const float4*)&W[tx][k4 * 4];
#pragma unroll
        for (int r = 0; r < 8; ++r) {
            float4 f = *(const float4*)&feat[ty * 8 + r][k4 * 4];
            acc[r] = fmaf(w.x, f.x, acc[r]);
            acc[r] = fmaf(w.y, f.y, acc[r]);
            acc[r] = fmaf(w.z, f.z, acc[r]);
            acc[r] = fmaf(w.w, f.w, acc[r]);
        }
    }
#pragma unroll
    for (int r = 0; r < 8; ++r) {
        int row = r0 + ty * 8 + r;
        float x = acc[r];
        __nv_bfloat16 h = __float2bfloat16_rn(x);
        __nv_bfloat16 l = __float2bfloat16_rn(x - __bfloat162float(h));
        __nv_bfloat16* dst = &g_predc[(size_t)row * KTOT];
        dst[c0 + tx] = h;
        dst[128 + c0 + tx] = h;
        dst[256 + c0 + tx] = l;
    }
}

// ---------------- kD: mma.sync bf16 GEMM (K=384) + online row-LSE ----------------
// Block tile 128i x 128j (warps 4x2, warp tile 32i x 64j), register-prefetched
// staging, NS=4 j-splits -> 128 blocks = single wave.
__global__ void __launch_bounds__(256) kD() {
    __shared__ __align__(16) __nv_bfloat16 sA[128 * SBPAD];
    __shared__ __align__(16) __nv_bfloat16 sB[128 * SBPAD];
    __shared__ float spm[128][8];
    __shared__ float spl[128][8];
    int tid = threadIdx.x;
    int warp = tid >> 5, lane = tid & 31;
    int wi = warp >> 1, wj = warp & 1;
    int i0 = blockIdx.x * 128;
    int by = blockIdx.y;
    uint32_t sAu = smem_u32(sA), sBu = smem_u32(sB);

    int ra[4], ca[4];
#pragma unroll
    for (int u = 0; u < 4; ++u) {
        int idx = tid + u * 256;
        ra[u] = idx >> 3;
        ca[u] = idx & 7;
    }

    float rm[4], rl[4];
#pragma unroll
    for (int s = 0; s < 4; ++s) { rm[s] = -1e30f; rl[s] = 0.f; }

    for (int jt = 0; jt < 8; ++jt) {
        int jbase = by * 1024 + jt * 128;
        float acc[2][8][4];
#pragma unroll
        for (int mf = 0; mf < 2; ++mf)
#pragma unroll
            for (int gg = 0; gg < 8; ++gg)
#pragma unroll
                for (int e = 0; e < 4; ++e) acc[mf][gg][e] = 0.f;

        uint4 pa[4], pb[4];
#pragma unroll
        for (int u = 0; u < 4; ++u) {
            pa[u] = *(const uint4*)&g_zwc[(size_t)(i0 + ra[u]) * KTOT + ca[u] * 8];
            pb[u] = *(const uint4*)&g_predc[(size_t)(jbase + ra[u]) * KTOT + ca[u] * 8];
        }

        for (int kc = 0; kc < KTOT; kc += KC) {
            __syncthreads();
#pragma unroll
            for (int u = 0; u < 4; ++u) {
                *(uint4*)&sA[ra[u] * SBPAD + ca[u] * 8] = pa[u];
                *(uint4*)&sB[ra[u] * SBPAD + ca[u] * 8] = pb[u];
            }
            __syncthreads();
            if (kc + KC < KTOT) {
                int kn = kc + KC;
#pragma unroll
                for (int u = 0; u < 4; ++u) {
                    pa[u] = *(const uint4*)&g_zwc[(size_t)(i0 + ra[u]) * KTOT + kn + ca[u] * 8];
                    pb[u] = *(const uint4*)&g_predc[(size_t)(jbase + ra[u]) * KTOT + kn + ca[u] * 8];
                }
            }
#pragma unroll
            for (int ks = 0; ks < 4; ++ks) {
                int kk = ks * 16;
                uint32_t a[2][4], bfr[8][2];
#pragma unroll
                for (int mf = 0; mf < 2; ++mf) {
                    uint32_t addr = sAu +
                        (uint32_t)(((wi * 32 + mf * 16 + (lane & 15)) * SBPAD +
                                    kk + (lane >> 4) * 8) * 2);
                    asm volatile(
                        "ldmatrix.sync.aligned.m8n8.x4.shared.b16 "
                        "{%0, %1, %2, %3}, [%4];"
                        : "=r"(a[mf][0]), "=r"(a[mf][1]),
                          "=r"(a[mf][2]), "=r"(a[mf][3])
                        : "r"(addr));
                }
#pragma unroll
                for (int gg = 0; gg < 8; ++gg) {
                    uint32_t addr = sBu +
                        (uint32_t)(((wj * 64 + gg * 8 + (lane & 7)) * SBPAD +
                                    kk + ((lane >> 3) & 1) * 8) * 2);
                    asm volatile(
                        "ldmatrix.sync.aligned.m8n8.x2.shared.b16 "
                        "{%0, %1}, [%2];"
                        : "=r"(bfr[gg][0]), "=r"(bfr[gg][1])
                        : "r"(addr));
                }
#pragma unroll
                for (int mf = 0; mf < 2; ++mf)
#pragma unroll
                    for (int gg = 0; gg < 8; ++gg) {
                        asm volatile(
                            "mma.sync.aligned.m16n8k16.row.col.f32.bf16.bf16.f32 "
                            "{%0, %1, %2, %3}, {%4, %5, %6, %7}, {%8, %9}, "
                            "{%0, %1, %2, %3};"
                            : "+f"(acc[mf][gg][0]), "+f"(acc[mf][gg][1]),
                              "+f"(acc[mf][gg][2]), "+f"(acc[mf][gg][3])
                            : "r"(a[mf][0]), "r"(a[mf][1]),
                              "r"(a[mf][2]), "r"(a[mf][3]),
                              "r"(bfr[gg][0]), "r"(bfr[gg][1]));
                    }
            }
        }
        // epilogue: online LSE per row-slot, diag capture
#pragma unroll
        for (int mf = 0; mf < 2; ++mf)
#pragma unroll
            for (int half = 0; half < 2; ++half) {
                int slot = mf * 2 + half;
                float v[16];
#pragma unroll
                for (int gg = 0; gg < 8; ++gg) {
                    v[gg * 2] = acc[mf][gg][half * 2];
                    v[gg * 2 + 1] = acc[mf][gg][half * 2 + 1];
                }
                float tmax = v[0];
#pragma unroll
                for (int u = 1; u < 16; ++u) tmax = fmaxf(tmax, v[u]);
                if (tmax > rm[slot]) {
                    rl[slot] *= __expf(rm[slot] - tmax);
                    rm[slot] = tmax;
                }
                float add = 0.f;
#pragma unroll
                for (int u = 0; u < 16; ++u) add += __expf(v[u] - rm[slot]);
                rl[slot] += add;
                int irow = i0 + wi * 32 + mf * 16 + half * 8 + (lane >> 2);
#pragma unroll
                for (int gg = 0; gg < 8; ++gg)
#pragma unroll
                    for (int e = 0; e < 2; ++e) {
                        int j = jbase + wj * 64 + gg * 8 + (lane & 3) * 2 + e;
                        if (j == irow) g_diag[irow] = v[gg * 2 + e];
                    }
            }
    }
    __syncthreads();
    // merge 8 partials per row
#pragma unroll
    for (int mf = 0; mf < 2; ++mf)
#pragma unroll
        for (int half = 0; half < 2; ++half) {
            int slot = mf * 2 + half;
            int row = wi * 32 + mf * 16 + half * 8 + (lane >> 2);
            int col = wj * 4 + (lane & 3);
            spm[row][col] = rm[slot];
            spl[row][col] = rl[slot];
        }
    __syncthreads();
    if (tid < 128) {
        float m = -1e30f;
#pragma unroll
        for (int t = 0; t < 8; ++t) m = fmaxf(m, spm[tid][t]);
        float l = 0.f;
#pragma unroll
        for (int t = 0; t < 8; ++t) l += spl[tid][t] * __expf(spm[tid][t] - m);
        int irow = i0 + tid;
        g_pm[irow * NS + by] = m;
        g_pl[irow * NS + by] = l;
    }
}

// ---------------- kE ----------------
__global__ void __launch_bounds__(1024) kE(float* out) {
    __shared__ float red[1024];
    int tid = threadIdx.x;
    float local = 0.f;
    for (int i = tid; i < B_TOT; i += 1024) {
        float m = -1e30f;
#pragma unroll
        for (int s = 0; s < NS; ++s) m = fmaxf(m, g_pm[i * NS + s]);
        float l = 0.f;
#pragma unroll
        for (int s = 0; s < NS; ++s) l += g_pl[i * NS + s] * __expf(g_pm[i * NS + s] - m);
        local += (m + logf(l)) - g_diag[i];
    }
    red[tid] = local;
    __syncthreads();
    for (int w = 512; w > 0; w >>= 1) {
        if (tid < w) red[tid] += red[tid + w];
        __syncthreads();
    }
    if (tid == 0) out[0] = red[0] / (float)B_TOT;
}

extern "C" void kernel_launch(void* const* d_in, const int* in_sizes, int n_in,
                              void* d_out, int out_size) {
    const float* zw0   = (const float*)d_in[0];
    const float* zw1   = (const float*)d_in[1];
    const float* c     = (const float*)d_in[2];
    const float* Wk_w  = (const float*)d_in[3];
    const float* Wk_b  = (const float*)d_in[4];
    const float* Ww0_w = (const float*)d_in[5];
    const float* Ww0_b = (const float*)d_in[6];
    const float* Ww1_w = (const float*)d_in[7];
    const float* Ww1_b = (const float*)d_in[8];
    const float* lin0_w = (const float*)d_in[9];
    const float* lin0_b = (const float*)d_in[10];
    const float* lin1_w = (const float*)d_in[11];
    const float* lin1_b = (const float*)d_in[12];
    const float* a01w = (const float*)d_in[13];
    const float* a01b = (const float*)d_in[14];
    const float* a02w = (const float*)d_in[15];
    const float* a02b = (const float*)d_in[16];
    const float* a11w = (const float*)d_in[17];
    const float* a11b = (const float*)d_in[18];
    const float* a12w = (const float*)d_in[19];
    const float* a12b = (const float*)d_in[20];

    kA1<<<128, 256>>>(zw0, zw1, lin0_w, lin0_b, lin1_w, lin1_b);
    kA2<<<128, 256>>>(a01w, a01b, a02w, a02b, a11w, a11b, a12w, a12b);
    kB0<<<2, 256>>>();
    kB1<<<dim3(16, 2), 256>>>();
    kB2<<<2, 64>>>();
    kC<<<dim3(128, 2), 256>>>(c, Wk_w, Wk_b, Ww0_w, Ww0_b, Ww1_w, Ww1_b);
    kD<<<dim3(32, NS), 256>>>();
    kE<<<1, 1024>>>((float*)d_out);
}